// round 1
// baseline (speedup 1.0000x reference)
#include <cuda_runtime.h>
#include <cstdint>

#define Bb 16
#define Ll 2048
#define Ee 1024
#define Dk 128
#define Mtot (Bb*Ll)   // 32768

// Scratch for projected Q, K, V (fp32). 3 x 16MB static device arrays.
__device__ float g_Q[Bb*Ll*Dk];
__device__ float g_K[Bb*Ll*Dk];
__device__ float g_V[Bb*Ll*Dk];

// ---------------------------------------------------------------------------
// Projection SGEMM: C[M=32768, N=128] = A[M,1024] @ W[1024,128], masked rows.
// Tile 128x128x16, 256 threads, 8x8 per-thread microtile.
// ---------------------------------------------------------------------------
__global__ __launch_bounds__(256) void proj_kernel(
    const float* __restrict__ A, const float* __restrict__ W,
    float* __restrict__ C, const int* __restrict__ lens)
{
    __shared__ float As[16][132];  // A tile, transposed [k][m], padded
    __shared__ float Bs[16][128];  // W tile [k][n]

    const int tid = threadIdx.x;
    const int m0  = blockIdx.x * 128;
    const int tr  = tid >> 4;      // 0..15 -> rows tr*8..+7
    const int tc  = tid & 15;      // 0..15 -> cols tc*8..+7

    float acc[8][8];
    #pragma unroll
    for (int i = 0; i < 8; i++)
        #pragma unroll
        for (int j = 0; j < 8; j++) acc[i][j] = 0.0f;

    for (int k0 = 0; k0 < Ee; k0 += 16) {
        // Load A tile: 128 rows x 16 cols = 512 float4, 2 per thread
        #pragma unroll
        for (int i = 0; i < 2; i++) {
            int f   = tid * 2 + i;
            int row = f >> 2;              // 4 float4 per row
            int kk  = (f & 3) << 2;
            float4 v = *(const float4*)(A + (size_t)(m0 + row) * Ee + k0 + kk);
            As[kk + 0][row] = v.x;
            As[kk + 1][row] = v.y;
            As[kk + 2][row] = v.z;
            As[kk + 3][row] = v.w;
        }
        // Load W tile: 16 rows x 128 cols = 512 float4, 2 per thread
        #pragma unroll
        for (int i = 0; i < 2; i++) {
            int f   = tid + i * 256;
            int row = f >> 5;              // 32 float4 per row
            int cc  = (f & 31) << 2;
            *(float4*)&Bs[row][cc] =
                *(const float4*)(W + (size_t)(k0 + row) * Dk + cc);
        }
        __syncthreads();

        #pragma unroll
        for (int k = 0; k < 16; k++) {
            float a[8], b[8];
            *(float4*)(a)     = *(const float4*)&As[k][tr * 8];
            *(float4*)(a + 4) = *(const float4*)&As[k][tr * 8 + 4];
            *(float4*)(b)     = *(const float4*)&Bs[k][tc * 8];
            *(float4*)(b + 4) = *(const float4*)&Bs[k][tc * 8 + 4];
            #pragma unroll
            for (int i = 0; i < 8; i++)
                #pragma unroll
                for (int j = 0; j < 8; j++)
                    acc[i][j] = fmaf(a[i], b[j], acc[i][j]);
        }
        __syncthreads();
    }

    // Epilogue: zero padded time steps (row l >= len[b])
    #pragma unroll
    for (int i = 0; i < 8; i++) {
        int row  = m0 + tr * 8 + i;
        int bb   = row >> 11;    // /2048
        int lpos = row & 2047;
        float mask = (lpos < lens[bb]) ? 1.0f : 0.0f;
        #pragma unroll
        for (int j = 0; j < 8; j += 4) {
            float4 v;
            v.x = acc[i][j + 0] * mask;
            v.y = acc[i][j + 1] * mask;
            v.z = acc[i][j + 2] * mask;
            v.w = acc[i][j + 3] * mask;
            *(float4*)(C + (size_t)row * Dk + tc * 8 + j) = v;
        }
    }
}

// ---------------------------------------------------------------------------
// Flash attention, fp32, causal + key-length mask.
// BQ=64 queries per block, BK=64 keys per iteration, 128 threads.
// Online softmax in log2 domain. K and V share one smem buffer.
// smem: Qs [64][132] + KV max(128*68, 64*128) + Ps [64][66] = 85504 bytes.
// ---------------------------------------------------------------------------
#define ATTN_SMEM_BYTES ((8448 + 8704 + 4224) * 4)

__global__ __launch_bounds__(128) void attn_kernel(
    const float* __restrict__ Q, const float* __restrict__ K,
    const float* __restrict__ V, float* __restrict__ Out,
    const int* __restrict__ lens)
{
    extern __shared__ float sm[];
    float* Qs = sm;                  // [64][132]
    float* KV = sm + 8448;           // K^T [128][68]  or  V [64][128]
    float* Ps = sm + 8448 + 8704;    // [64][66]

    const int b   = blockIdx.y;
    const int q0  = blockIdx.x * 64;
    const int tid = threadIdx.x;
    const int tr  = tid >> 3;        // 0..15 -> rows tr*4..+3
    const int tc  = tid & 7;         // 0..7
    const int r0  = tr * 4;
    const int c0  = tc * 8;          // S columns for this thread
    const int len = lens[b];

    // Pre-scale Q by log2(e)/sqrt(dk) so softmax uses exp2f
    const float qscale = 1.4426950408889634f / 11.313708498984761f;

    const float* Qg = Q + ((size_t)(b * Ll + q0)) * Dk;
    for (int f = tid; f < 2048; f += 128) {     // 64 rows x 32 float4
        int r = f >> 5;
        int c = (f & 31) << 2;
        float4 v = *(const float4*)(Qg + r * Dk + c);
        float* d = Qs + r * 132 + c;
        d[0] = v.x * qscale; d[1] = v.y * qscale;
        d[2] = v.z * qscale; d[3] = v.w * qscale;
    }

    float m[4], l[4], acc[4][16];
    #pragma unroll
    for (int i = 0; i < 4; i++) {
        m[i] = -1e30f; l[i] = 0.0f;
        #pragma unroll
        for (int j = 0; j < 16; j++) acc[i][j] = 0.0f;
    }

    const int kend = min(len, q0 + 64);   // len >= 1, so kend >= 1
    __syncthreads();

    for (int j0 = 0; j0 < kend; j0 += 64) {
        // --- Load K tile transposed: KV[d][k] = K[j0+k][d] ---
        const float* Kg = K + ((size_t)(b * Ll + j0)) * Dk;
        for (int f = tid; f < 2048; f += 128) {
            int r = f >> 5;               // key row 0..63
            int c = (f & 31) << 2;        // d 0..124
            float4 v = *(const float4*)(Kg + r * Dk + c);
            KV[(c + 0) * 68 + r] = v.x;
            KV[(c + 1) * 68 + r] = v.y;
            KV[(c + 2) * 68 + r] = v.z;
            KV[(c + 3) * 68 + r] = v.w;
        }
        __syncthreads();

        // --- S = Q K^T  (thread computes 4x8 tile) ---
        float s[4][8];
        #pragma unroll
        for (int i = 0; i < 4; i++)
            #pragma unroll
            for (int j = 0; j < 8; j++) s[i][j] = 0.0f;

        #pragma unroll 4
        for (int d0 = 0; d0 < 128; d0 += 4) {
            float4 qv[4];
            #pragma unroll
            for (int i = 0; i < 4; i++)
                qv[i] = *(const float4*)(Qs + (r0 + i) * 132 + d0);
            #pragma unroll
            for (int i2 = 0; i2 < 4; i2++) {
                float4 ka = *(const float4*)(KV + (d0 + i2) * 68 + c0);
                float4 kb = *(const float4*)(KV + (d0 + i2) * 68 + c0 + 4);
                float kvv[8] = {ka.x, ka.y, ka.z, ka.w, kb.x, kb.y, kb.z, kb.w};
                #pragma unroll
                for (int i = 0; i < 4; i++) {
                    float qd = (i2 == 0) ? qv[i].x :
                               (i2 == 1) ? qv[i].y :
                               (i2 == 2) ? qv[i].z : qv[i].w;
                    #pragma unroll
                    for (int j = 0; j < 8; j++)
                        s[i][j] = fmaf(qd, kvv[j], s[i][j]);
                }
            }
        }

        // --- mask + online softmax (row groups of 8 lanes share a row) ---
        #pragma unroll
        for (int i = 0; i < 4; i++) {
            int qi = q0 + r0 + i;
            float sv[8];
            float mx = -1e30f;
            #pragma unroll
            for (int j = 0; j < 8; j++) {
                int ki = j0 + c0 + j;
                float vv = (ki <= qi && ki < len) ? s[i][j] : -1e30f;
                sv[j] = vv;
                mx = fmaxf(mx, vv);
            }
            #pragma unroll
            for (int off = 1; off < 8; off <<= 1)
                mx = fmaxf(mx, __shfl_xor_sync(0xffffffffu, mx, off));
            float mnew  = fmaxf(m[i], mx);
            float alpha = exp2f(m[i] - mnew);
            float lsum  = 0.0f;
            #pragma unroll
            for (int j = 0; j < 8; j++) {
                float p = exp2f(sv[j] - mnew);
                Ps[(r0 + i) * 66 + c0 + j] = p;
                lsum += p;
            }
            #pragma unroll
            for (int off = 1; off < 8; off <<= 1)
                lsum += __shfl_xor_sync(0xffffffffu, lsum, off);
            l[i] = l[i] * alpha + lsum;
            m[i] = mnew;
            #pragma unroll
            for (int j = 0; j < 16; j++) acc[i][j] *= alpha;
        }
        __syncthreads();

        // --- Load V tile (reuses KV buffer): KV[k][d] ---
        const float* Vg = V + ((size_t)(b * Ll + j0)) * Dk;
        for (int f = tid; f < 2048; f += 128) {
            int r = f >> 5;
            int c = (f & 31) << 2;
            *(float4*)(KV + r * Dk + c) = *(const float4*)(Vg + r * Dk + c);
        }
        __syncthreads();

        // --- O += P @ V  (thread owns cols tc*4 + 32*jj, jj=0..3) ---
        #pragma unroll 2
        for (int k = 0; k < 64; k++) {
            float p[4];
            #pragma unroll
            for (int i = 0; i < 4; i++) p[i] = Ps[(r0 + i) * 66 + k];
            #pragma unroll
            for (int jj = 0; jj < 4; jj++) {
                float4 v = *(const float4*)(KV + k * Dk + tc * 4 + jj * 32);
                #pragma unroll
                for (int i = 0; i < 4; i++) {
                    acc[i][jj * 4 + 0] = fmaf(p[i], v.x, acc[i][jj * 4 + 0]);
                    acc[i][jj * 4 + 1] = fmaf(p[i], v.y, acc[i][jj * 4 + 1]);
                    acc[i][jj * 4 + 2] = fmaf(p[i], v.z, acc[i][jj * 4 + 2]);
                    acc[i][jj * 4 + 3] = fmaf(p[i], v.w, acc[i][jj * 4 + 3]);
                }
            }
        }
        __syncthreads();
    }

    // --- normalize + write ---
    #pragma unroll
    for (int i = 0; i < 4; i++) {
        float inv = 1.0f / l[i];
        size_t base = ((size_t)(b * Ll + q0 + r0 + i)) * Dk;
        #pragma unroll
        for (int jj = 0; jj < 4; jj++) {
            float4 v;
            v.x = acc[i][jj * 4 + 0] * inv;
            v.y = acc[i][jj * 4 + 1] * inv;
            v.z = acc[i][jj * 4 + 2] * inv;
            v.w = acc[i][jj * 4 + 3] * inv;
            *(float4*)(Out + base + tc * 4 + jj * 32) = v;
        }
    }
}

// ---------------------------------------------------------------------------
extern "C" void kernel_launch(void* const* d_in, const int* in_sizes, int n_in,
                              void* d_out, int out_size)
{
    const float* x    = (const float*)d_in[0];
    const float* ctx  = (const float*)d_in[1];
    const int*   lens = (const int*)  d_in[2];
    const float* Wq   = (const float*)d_in[3];
    const float* Wk   = (const float*)d_in[4];
    const float* Wv   = (const float*)d_in[5];
    float* out = (float*)d_out;
    (void)in_sizes; (void)n_in; (void)out_size;

    float *pQ, *pK, *pV;
    cudaGetSymbolAddress((void**)&pQ, g_Q);
    cudaGetSymbolAddress((void**)&pK, g_K);
    cudaGetSymbolAddress((void**)&pV, g_V);

    proj_kernel<<<Mtot / 128, 256>>>(ctx, Wq, pQ, lens);
    proj_kernel<<<Mtot / 128, 256>>>(ctx, Wk, pK, lens);
    proj_kernel<<<Mtot / 128, 256>>>(x,   Wv, pV, lens);

    cudaFuncSetAttribute(attn_kernel,
                         cudaFuncAttributeMaxDynamicSharedMemorySize,
                         ATTN_SMEM_BYTES);
    attn_kernel<<<dim3(Ll / 64, Bb), 128, ATTN_SMEM_BYTES>>>(pQ, pK, pV, out, lens);
}

// round 3
// speedup vs baseline: 2.4321x; 2.4321x over previous
#include <cuda_runtime.h>
#include <cuda_bf16.h>
#include <cstdint>

#define Bb 16
#define Ll 2048
#define Ee 1024
#define Dk 128
#define Mtot (Bb*Ll)   // 32768

// Scratch: projected Q, K, V (fp32) + split/transposed weights (bf16 hi/lo).
__device__ float g_Q[Bb*Ll*Dk];
__device__ float g_K[Bb*Ll*Dk];
__device__ float g_V[Bb*Ll*Dk];
// g_Wt layout: [mat(3)][hi/lo(2)][N=128][K=1024] bf16  (i.e. B in column-major)
__device__ __nv_bfloat16 g_Wt[3 * 2 * 128 * 1024];

__device__ __forceinline__ uint32_t smem_u32(const void* p) {
    uint32_t a;
    asm("{ .reg .u64 t; cvta.to.shared.u64 t, %1; cvt.u32.u64 %0, t; }"
        : "=r"(a) : "l"(p));
    return a;
}

#define LDMX4(r, addr) \
    asm volatile("ldmatrix.sync.aligned.m8n8.x4.shared.b16 {%0,%1,%2,%3}, [%4];" \
        : "=r"((r)[0]), "=r"((r)[1]), "=r"((r)[2]), "=r"((r)[3]) : "r"(addr))

#define MMA16816(d, a, b0, b1) \
    asm volatile("mma.sync.aligned.m16n8k16.row.col.f32.bf16.bf16.f32 " \
        "{%0,%1,%2,%3}, {%4,%5,%6,%7}, {%8,%9}, {%0,%1,%2,%3};" \
        : "+f"((d)[0]), "+f"((d)[1]), "+f"((d)[2]), "+f"((d)[3]) \
        : "r"((a)[0]), "r"((a)[1]), "r"((a)[2]), "r"((a)[3]), "r"(b0), "r"(b1))

// ---------------------------------------------------------------------------
// Weight prep: W[1024,128] fp32 -> Wt_hi[n][k], Wt_lo[n][k] bf16 (transposed)
// ---------------------------------------------------------------------------
__global__ void prep_weights(const float* __restrict__ Wq,
                             const float* __restrict__ Wk,
                             const float* __restrict__ Wv)
{
    __shared__ float t[32][33];
    const int mat = blockIdx.z;
    const float* W = (mat == 0) ? Wq : (mat == 1) ? Wk : Wv;
    const int k0 = blockIdx.x * 32, n0 = blockIdx.y * 32;
    const int tx = threadIdx.x, ty = threadIdx.y;
    t[ty][tx] = W[(size_t)(k0 + ty) * Dk + n0 + tx];
    __syncthreads();
    float v = t[tx][ty];
    __nv_bfloat16 hi = __float2bfloat16(v);
    float lo = v - __bfloat162float(hi);
    __nv_bfloat16* dst = g_Wt + (size_t)mat * 262144;
    size_t o = (size_t)(n0 + ty) * Ee + k0 + tx;
    dst[o] = hi;
    dst[131072 + o] = __float2bfloat16(lo);
}

// ---------------------------------------------------------------------------
// Projection GEMM via warp-level mma.sync (bf16x3 split, fp32 accum in regs).
// CTA: 128x128 tile; 8 warps in 4x2 grid, each 32x64.
// K-chunk 32, double-buffered smem, one barrier per chunk.
// Stage layout (bytes, pitch 80B = 40 bf16 per row):
//   A_hi 0 .. 10240, A_lo 10240.., W_hi 20480.., W_lo 30720..; stage = 40960.
// ---------------------------------------------------------------------------
#define PROJ_SMEM (2 * 40960)

__global__ __launch_bounds__(256, 1) void proj_mma(
    const float* __restrict__ x, const float* __restrict__ ctx,
    const int* __restrict__ lens)
{
    extern __shared__ char smraw[];
    const int tid  = threadIdx.x;
    const int lane = tid & 31;
    const int wid  = tid >> 5;
    const int wm   = wid >> 1;      // 0..3 -> 32-row band
    const int wn   = wid & 1;       // 0..1 -> 64-col band
    const int mat  = blockIdx.y;
    const int m0   = blockIdx.x * 128;
    const float* A = (mat == 2) ? x : ctx;
    float* C = (mat == 0) ? g_Q : (mat == 1) ? g_K : g_V;
    const __nv_bfloat16* Wh = g_Wt + (size_t)mat * 262144;
    const __nv_bfloat16* Wl = Wh + 131072;

    const uint32_t sbase = smem_u32(smraw);

    float acc[2][8][4];
    #pragma unroll
    for (int mt = 0; mt < 2; mt++)
        #pragma unroll
        for (int nt = 0; nt < 8; nt++)
            #pragma unroll
            for (int j = 0; j < 4; j++) acc[mt][nt][j] = 0.0f;

    // ldmatrix lane-address components
    const uint32_t a_row  = (uint32_t)(lane & 15);
    const uint32_t a_col2 = (uint32_t)((lane >> 4) << 3) * 2;     // bytes
    const uint32_t b_row  = (uint32_t)((lane & 7) + ((lane >> 4) << 3));
    const uint32_t b_col2 = (uint32_t)(((lane >> 3) & 1) << 3) * 2;

    float4 ar[4];
    uint4  wr[4];

    // global -> regs for chunk at element offset k0 (32 wide)
    auto load_regs = [&](int k0) {
        #pragma unroll
        for (int i = 0; i < 4; i++) {
            int f = tid + i * 256;          // 0..1023
            int row = f >> 3, c4 = f & 7;
            ar[i] = *(const float4*)(A + (size_t)(m0 + row) * Ee + k0 + c4 * 4);
        }
        #pragma unroll
        for (int i = 0; i < 2; i++) {
            int f = tid + i * 256;          // 0..511
            int row = f >> 2, q = f & 3;
            wr[i]     = *(const uint4*)(Wh + (size_t)row * Ee + k0 + q * 8);
            wr[i + 2] = *(const uint4*)(Wl + (size_t)row * Ee + k0 + q * 8);
        }
    };

    // regs -> smem stage (with fp32 -> bf16 hi/lo split for A)
    auto st_stage = [&](int buf) {
        char* tb = smraw + buf * 40960;
        #pragma unroll
        for (int i = 0; i < 4; i++) {
            int f = tid + i * 256;
            int row = f >> 3, c4 = f & 7;
            float4 v = ar[i];
            __nv_bfloat162 h0 = __float22bfloat162_rn(make_float2(v.x, v.y));
            __nv_bfloat162 h1 = __float22bfloat162_rn(make_float2(v.z, v.w));
            float2 f0 = __bfloat1622float2(h0);
            float2 f1 = __bfloat1622float2(h1);
            __nv_bfloat162 l0 =
                __float22bfloat162_rn(make_float2(v.x - f0.x, v.y - f0.y));
            __nv_bfloat162 l1 =
                __float22bfloat162_rn(make_float2(v.z - f1.x, v.w - f1.y));
            uint2 hv, lv;
            hv.x = *(uint32_t*)&h0; hv.y = *(uint32_t*)&h1;
            lv.x = *(uint32_t*)&l0; lv.y = *(uint32_t*)&l1;
            uint32_t off = row * 80 + c4 * 8;
            *(uint2*)(tb + off)         = hv;
            *(uint2*)(tb + 10240 + off) = lv;
        }
        #pragma unroll
        for (int i = 0; i < 2; i++) {
            int f = tid + i * 256;
            int row = f >> 2, q = f & 3;
            uint32_t off = row * 80 + q * 16;
            *(uint4*)(tb + 20480 + off) = wr[i];
            *(uint4*)(tb + 30720 + off) = wr[i + 2];
        }
    };

    auto do_mma = [&](int buf) {
        const uint32_t st = sbase + buf * 40960;
        #pragma unroll
        for (int ks = 0; ks < 2; ks++) {
            const uint32_t kk2 = ks * 32;   // k-step offset in bytes (16 elems)
            uint32_t ah[2][4], al[2][4];
            #pragma unroll
            for (int mt = 0; mt < 2; mt++) {
                uint32_t r = wm * 32 + mt * 16 + a_row;
                uint32_t addr = st + r * 80 + kk2 + a_col2;
                LDMX4(ah[mt], addr);
                LDMX4(al[mt], addr + 10240);
            }
            #pragma unroll
            for (int p = 0; p < 4; p++) {
                uint32_t nr = wn * 64 + p * 16 + b_row;
                uint32_t addr = st + 20480 + nr * 80 + kk2 + b_col2;
                uint32_t bh[4], bl[4];
                LDMX4(bh, addr);
                LDMX4(bl, addr + 10240);
                #pragma unroll
                for (int mt = 0; mt < 2; mt++) {
                    MMA16816(acc[mt][2*p],     ah[mt], bh[0], bh[1]);
                    MMA16816(acc[mt][2*p + 1], ah[mt], bh[2], bh[3]);
                    MMA16816(acc[mt][2*p],     ah[mt], bl[0], bl[1]);
                    MMA16816(acc[mt][2*p + 1], ah[mt], bl[2], bl[3]);
                    MMA16816(acc[mt][2*p],     al[mt], bh[0], bh[1]);
                    MMA16816(acc[mt][2*p + 1], al[mt], bh[2], bh[3]);
                }
            }
        }
    };

    load_regs(0);
    for (int c = 0; c < 32; c++) {
        st_stage(c & 1);
        __syncthreads();
        if (c < 31) load_regs((c + 1) * 32);
        do_mma(c & 1);
    }

    // Epilogue: masked fp32 store. Thread holds C(rows r, r+8; cols cc, cc+1).
    const int lenb = lens[m0 >> 11];
    #pragma unroll
    for (int mt = 0; mt < 2; mt++) {
        int r = m0 + wm * 32 + mt * 16 + (lane >> 2);
        float mk0 = (((r)     & 2047) < lenb) ? 1.0f : 0.0f;
        float mk1 = (((r + 8) & 2047) < lenb) ? 1.0f : 0.0f;
        #pragma unroll
        for (int nt = 0; nt < 8; nt++) {
            int cc = wn * 64 + nt * 8 + (lane & 3) * 2;
            float2 v0, v1;
            v0.x = acc[mt][nt][0] * mk0; v0.y = acc[mt][nt][1] * mk0;
            v1.x = acc[mt][nt][2] * mk1; v1.y = acc[mt][nt][3] * mk1;
            *(float2*)(C + (size_t)r * Dk + cc)        = v0;
            *(float2*)(C + (size_t)(r + 8) * Dk + cc)  = v1;
        }
    }
}

// ---------------------------------------------------------------------------
// Flash attention, fp32 (unchanged from R1 — 927us, next target).
// ---------------------------------------------------------------------------
#define ATTN_SMEM_BYTES ((8448 + 8704 + 4224) * 4)

__global__ __launch_bounds__(128) void attn_kernel(
    const float* __restrict__ Q, const float* __restrict__ K,
    const float* __restrict__ V, float* __restrict__ Out,
    const int* __restrict__ lens)
{
    extern __shared__ float sm[];
    float* Qs = sm;                  // [64][132]
    float* KV = sm + 8448;           // K^T [128][68]  or  V [64][128]
    float* Ps = sm + 8448 + 8704;    // [64][66]

    const int b   = blockIdx.y;
    const int q0  = blockIdx.x * 64;
    const int tid = threadIdx.x;
    const int tr  = tid >> 3;
    const int tc  = tid & 7;
    const int r0  = tr * 4;
    const int c0  = tc * 8;
    const int len = lens[b];

    const float qscale = 1.4426950408889634f / 11.313708498984761f;

    const float* Qg = Q + ((size_t)(b * Ll + q0)) * Dk;
    for (int f = tid; f < 2048; f += 128) {
        int r = f >> 5;
        int c = (f & 31) << 2;
        float4 v = *(const float4*)(Qg + r * Dk + c);
        float* d = Qs + r * 132 + c;
        d[0] = v.x * qscale; d[1] = v.y * qscale;
        d[2] = v.z * qscale; d[3] = v.w * qscale;
    }

    float m[4], l[4], acc[4][16];
    #pragma unroll
    for (int i = 0; i < 4; i++) {
        m[i] = -1e30f; l[i] = 0.0f;
        #pragma unroll
        for (int j = 0; j < 16; j++) acc[i][j] = 0.0f;
    }

    const int kend = min(len, q0 + 64);
    __syncthreads();

    for (int j0 = 0; j0 < kend; j0 += 64) {
        const float* Kg = K + ((size_t)(b * Ll + j0)) * Dk;
        for (int f = tid; f < 2048; f += 128) {
            int r = f >> 5;
            int c = (f & 31) << 2;
            float4 v = *(const float4*)(Kg + r * Dk + c);
            KV[(c + 0) * 68 + r] = v.x;
            KV[(c + 1) * 68 + r] = v.y;
            KV[(c + 2) * 68 + r] = v.z;
            KV[(c + 3) * 68 + r] = v.w;
        }
        __syncthreads();

        float s[4][8];
        #pragma unroll
        for (int i = 0; i < 4; i++)
            #pragma unroll
            for (int j = 0; j < 8; j++) s[i][j] = 0.0f;

        #pragma unroll 4
        for (int d0 = 0; d0 < 128; d0 += 4) {
            float4 qv[4];
            #pragma unroll
            for (int i = 0; i < 4; i++)
                qv[i] = *(const float4*)(Qs + (r0 + i) * 132 + d0);
            #pragma unroll
            for (int i2 = 0; i2 < 4; i2++) {
                float4 ka = *(const float4*)(KV + (d0 + i2) * 68 + c0);
                float4 kb = *(const float4*)(KV + (d0 + i2) * 68 + c0 + 4);
                float kvv[8] = {ka.x, ka.y, ka.z, ka.w, kb.x, kb.y, kb.z, kb.w};
                #pragma unroll
                for (int i = 0; i < 4; i++) {
                    float qd = (i2 == 0) ? qv[i].x :
                               (i2 == 1) ? qv[i].y :
                               (i2 == 2) ? qv[i].z : qv[i].w;
                    #pragma unroll
                    for (int j = 0; j < 8; j++)
                        s[i][j] = fmaf(qd, kvv[j], s[i][j]);
                }
            }
        }

        #pragma unroll
        for (int i = 0; i < 4; i++) {
            int qi = q0 + r0 + i;
            float sv[8];
            float mx = -1e30f;
            #pragma unroll
            for (int j = 0; j < 8; j++) {
                int ki = j0 + c0 + j;
                float vv = (ki <= qi && ki < len) ? s[i][j] : -1e30f;
                sv[j] = vv;
                mx = fmaxf(mx, vv);
            }
            #pragma unroll
            for (int off = 1; off < 8; off <<= 1)
                mx = fmaxf(mx, __shfl_xor_sync(0xffffffffu, mx, off));
            float mnew  = fmaxf(m[i], mx);
            float alpha = exp2f(m[i] - mnew);
            float lsum  = 0.0f;
            #pragma unroll
            for (int j = 0; j < 8; j++) {
                float p = exp2f(sv[j] - mnew);
                Ps[(r0 + i) * 66 + c0 + j] = p;
                lsum += p;
            }
            #pragma unroll
            for (int off = 1; off < 8; off <<= 1)
                lsum += __shfl_xor_sync(0xffffffffu, lsum, off);
            l[i] = l[i] * alpha + lsum;
            m[i] = mnew;
            #pragma unroll
            for (int j = 0; j < 16; j++) acc[i][j] *= alpha;
        }
        __syncthreads();

        const float* Vg = V + ((size_t)(b * Ll + j0)) * Dk;
        for (int f = tid; f < 2048; f += 128) {
            int r = f >> 5;
            int c = (f & 31) << 2;
            *(float4*)(KV + r * Dk + c) = *(const float4*)(Vg + r * Dk + c);
        }
        __syncthreads();

        #pragma unroll 2
        for (int k = 0; k < 64; k++) {
            float p[4];
            #pragma unroll
            for (int i = 0; i < 4; i++) p[i] = Ps[(r0 + i) * 66 + k];
            #pragma unroll
            for (int jj = 0; jj < 4; jj++) {
                float4 v = *(const float4*)(KV + k * Dk + tc * 4 + jj * 32);
                #pragma unroll
                for (int i = 0; i < 4; i++) {
                    acc[i][jj * 4 + 0] = fmaf(p[i], v.x, acc[i][jj * 4 + 0]);
                    acc[i][jj * 4 + 1] = fmaf(p[i], v.y, acc[i][jj * 4 + 1]);
                    acc[i][jj * 4 + 2] = fmaf(p[i], v.z, acc[i][jj * 4 + 2]);
                    acc[i][jj * 4 + 3] = fmaf(p[i], v.w, acc[i][jj * 4 + 3]);
                }
            }
        }
        __syncthreads();
    }

    #pragma unroll
    for (int i = 0; i < 4; i++) {
        float inv = 1.0f / l[i];
        size_t base = ((size_t)(b * Ll + q0 + r0 + i)) * Dk;
        #pragma unroll
        for (int jj = 0; jj < 4; jj++) {
            float4 v;
            v.x = acc[i][jj * 4 + 0] * inv;
            v.y = acc[i][jj * 4 + 1] * inv;
            v.z = acc[i][jj * 4 + 2] * inv;
            v.w = acc[i][jj * 4 + 3] * inv;
            *(float4*)(Out + base + tc * 4 + jj * 32) = v;
        }
    }
}

// ---------------------------------------------------------------------------
extern "C" void kernel_launch(void* const* d_in, const int* in_sizes, int n_in,
                              void* d_out, int out_size)
{
    const float* x    = (const float*)d_in[0];
    const float* ctx  = (const float*)d_in[1];
    const int*   lens = (const int*)  d_in[2];
    const float* Wq   = (const float*)d_in[3];
    const float* Wk   = (const float*)d_in[4];
    const float* Wv   = (const float*)d_in[5];
    float* out = (float*)d_out;
    (void)in_sizes; (void)n_in; (void)out_size;

    float *pQ, *pK, *pV;
    cudaGetSymbolAddress((void**)&pQ, g_Q);
    cudaGetSymbolAddress((void**)&pK, g_K);
    cudaGetSymbolAddress((void**)&pV, g_V);

    prep_weights<<<dim3(32, 4, 3), dim3(32, 32)>>>(Wq, Wk, Wv);

    cudaFuncSetAttribute(proj_mma,
                         cudaFuncAttributeMaxDynamicSharedMemorySize, PROJ_SMEM);
    proj_mma<<<dim3(Mtot / 128, 3), 256, PROJ_SMEM>>>(x, ctx, lens);

    cudaFuncSetAttribute(attn_kernel,
                         cudaFuncAttributeMaxDynamicSharedMemorySize,
                         ATTN_SMEM_BYTES);
    attn_kernel<<<dim3(Ll / 64, Bb), 128, ATTN_SMEM_BYTES>>>(pQ, pK, pV, out, lens);
}

// round 4
// speedup vs baseline: 4.8615x; 1.9989x over previous
#include <cuda_runtime.h>
#include <cuda_bf16.h>
#include <cstdint>

#define Bb 16
#define Ll 2048
#define Ee 1024
#define Dk 128
#define Mtot (Bb*Ll)   // 32768

// Scratch: projected Q, K, V (fp32) + split/transposed weights (bf16 hi/lo).
__device__ float g_Q[Bb*Ll*Dk];
__device__ float g_K[Bb*Ll*Dk];
__device__ float g_V[Bb*Ll*Dk];
// g_Wt layout: [mat(3)][hi/lo(2)][N=128][K=1024] bf16  (B in column-major)
__device__ __nv_bfloat16 g_Wt[3 * 2 * 128 * 1024];

__device__ __forceinline__ uint32_t smem_u32(const void* p) {
    uint32_t a;
    asm("{ .reg .u64 t; cvta.to.shared.u64 t, %1; cvt.u32.u64 %0, t; }"
        : "=r"(a) : "l"(p));
    return a;
}

#define LDMX4(r, addr) \
    asm volatile("ldmatrix.sync.aligned.m8n8.x4.shared.b16 {%0,%1,%2,%3}, [%4];" \
        : "=r"((r)[0]), "=r"((r)[1]), "=r"((r)[2]), "=r"((r)[3]) : "r"(addr))

#define LDMX4T(r, addr) \
    asm volatile("ldmatrix.sync.aligned.m8n8.x4.trans.shared.b16 {%0,%1,%2,%3}, [%4];" \
        : "=r"((r)[0]), "=r"((r)[1]), "=r"((r)[2]), "=r"((r)[3]) : "r"(addr))

#define MMA16816(d, a, b0, b1) \
    asm volatile("mma.sync.aligned.m16n8k16.row.col.f32.bf16.bf16.f32 " \
        "{%0,%1,%2,%3}, {%4,%5,%6,%7}, {%8,%9}, {%0,%1,%2,%3};" \
        : "+f"((d)[0]), "+f"((d)[1]), "+f"((d)[2]), "+f"((d)[3]) \
        : "r"((a)[0]), "r"((a)[1]), "r"((a)[2]), "r"((a)[3]), "r"(b0), "r"(b1))

// fp32x4 -> bf16 hi/lo split, 8B stores
__device__ __forceinline__ void split_store(char* hi, char* lo, uint32_t off, float4 v) {
    __nv_bfloat162 h0 = __float22bfloat162_rn(make_float2(v.x, v.y));
    __nv_bfloat162 h1 = __float22bfloat162_rn(make_float2(v.z, v.w));
    float2 f0 = __bfloat1622float2(h0), f1 = __bfloat1622float2(h1);
    __nv_bfloat162 l0 = __float22bfloat162_rn(make_float2(v.x - f0.x, v.y - f0.y));
    __nv_bfloat162 l1 = __float22bfloat162_rn(make_float2(v.z - f1.x, v.w - f1.y));
    uint2 hv, lv;
    hv.x = *(uint32_t*)&h0; hv.y = *(uint32_t*)&h1;
    lv.x = *(uint32_t*)&l0; lv.y = *(uint32_t*)&l1;
    *(uint2*)(hi + off) = hv;
    *(uint2*)(lo + off) = lv;
}

// ---------------------------------------------------------------------------
// Weight prep: W[1024,128] fp32 -> Wt_hi[n][k], Wt_lo[n][k] bf16 (transposed)
// ---------------------------------------------------------------------------
__global__ void prep_weights(const float* __restrict__ Wq,
                             const float* __restrict__ Wk,
                             const float* __restrict__ Wv)
{
    __shared__ float t[32][33];
    const int mat = blockIdx.z;
    const float* W = (mat == 0) ? Wq : (mat == 1) ? Wk : Wv;
    const int k0 = blockIdx.x * 32, n0 = blockIdx.y * 32;
    const int tx = threadIdx.x, ty = threadIdx.y;
    t[ty][tx] = W[(size_t)(k0 + ty) * Dk + n0 + tx];
    __syncthreads();
    float v = t[tx][ty];
    __nv_bfloat16 hi = __float2bfloat16(v);
    float lo = v - __bfloat162float(hi);
    __nv_bfloat16* dst = g_Wt + (size_t)mat * 262144;
    size_t o = (size_t)(n0 + ty) * Ee + k0 + tx;
    dst[o] = hi;
    dst[131072 + o] = __float2bfloat16(lo);
}

// ---------------------------------------------------------------------------
// Projection GEMM via warp-level mma.sync (bf16x3 split) — unchanged from R3.
// ---------------------------------------------------------------------------
#define PROJ_SMEM (2 * 40960)

__global__ __launch_bounds__(256, 1) void proj_mma(
    const float* __restrict__ x, const float* __restrict__ ctx,
    const int* __restrict__ lens)
{
    extern __shared__ char smraw[];
    const int tid  = threadIdx.x;
    const int lane = tid & 31;
    const int wid  = tid >> 5;
    const int wm   = wid >> 1;
    const int wn   = wid & 1;
    const int mat  = blockIdx.y;
    const int m0   = blockIdx.x * 128;
    const float* A = (mat == 2) ? x : ctx;
    float* C = (mat == 0) ? g_Q : (mat == 1) ? g_K : g_V;
    const __nv_bfloat16* Wh = g_Wt + (size_t)mat * 262144;
    const __nv_bfloat16* Wl = Wh + 131072;

    const uint32_t sbase = smem_u32(smraw);

    float acc[2][8][4];
    #pragma unroll
    for (int mt = 0; mt < 2; mt++)
        #pragma unroll
        for (int nt = 0; nt < 8; nt++)
            #pragma unroll
            for (int j = 0; j < 4; j++) acc[mt][nt][j] = 0.0f;

    const uint32_t a_row  = (uint32_t)(lane & 15);
    const uint32_t a_col2 = (uint32_t)((lane >> 4) << 3) * 2;
    const uint32_t b_row  = (uint32_t)((lane & 7) + ((lane >> 4) << 3));
    const uint32_t b_col2 = (uint32_t)(((lane >> 3) & 1) << 3) * 2;

    float4 ar[4];
    uint4  wr[4];

    auto load_regs = [&](int k0) {
        #pragma unroll
        for (int i = 0; i < 4; i++) {
            int f = tid + i * 256;
            int row = f >> 3, c4 = f & 7;
            ar[i] = *(const float4*)(A + (size_t)(m0 + row) * Ee + k0 + c4 * 4);
        }
        #pragma unroll
        for (int i = 0; i < 2; i++) {
            int f = tid + i * 256;
            int row = f >> 2, q = f & 3;
            wr[i]     = *(const uint4*)(Wh + (size_t)row * Ee + k0 + q * 8);
            wr[i + 2] = *(const uint4*)(Wl + (size_t)row * Ee + k0 + q * 8);
        }
    };

    auto st_stage = [&](int buf) {
        char* tb = smraw + buf * 40960;
        #pragma unroll
        for (int i = 0; i < 4; i++) {
            int f = tid + i * 256;
            int row = f >> 3, c4 = f & 7;
            split_store(tb, tb + 10240, row * 80 + c4 * 8, ar[i]);
        }
        #pragma unroll
        for (int i = 0; i < 2; i++) {
            int f = tid + i * 256;
            int row = f >> 2, q = f & 3;
            uint32_t off = row * 80 + q * 16;
            *(uint4*)(tb + 20480 + off) = wr[i];
            *(uint4*)(tb + 30720 + off) = wr[i + 2];
        }
    };

    auto do_mma = [&](int buf) {
        const uint32_t st = sbase + buf * 40960;
        #pragma unroll
        for (int ks = 0; ks < 2; ks++) {
            const uint32_t kk2 = ks * 32;
            uint32_t ah[2][4], al[2][4];
            #pragma unroll
            for (int mt = 0; mt < 2; mt++) {
                uint32_t r = wm * 32 + mt * 16 + a_row;
                uint32_t addr = st + r * 80 + kk2 + a_col2;
                LDMX4(ah[mt], addr);
                LDMX4(al[mt], addr + 10240);
            }
            #pragma unroll
            for (int p = 0; p < 4; p++) {
                uint32_t nr = wn * 64 + p * 16 + b_row;
                uint32_t addr = st + 20480 + nr * 80 + kk2 + b_col2;
                uint32_t bh[4], bl[4];
                LDMX4(bh, addr);
                LDMX4(bl, addr + 10240);
                #pragma unroll
                for (int mt = 0; mt < 2; mt++) {
                    MMA16816(acc[mt][2*p],     ah[mt], bh[0], bh[1]);
                    MMA16816(acc[mt][2*p + 1], ah[mt], bh[2], bh[3]);
                    MMA16816(acc[mt][2*p],     ah[mt], bl[0], bl[1]);
                    MMA16816(acc[mt][2*p + 1], ah[mt], bl[2], bl[3]);
                    MMA16816(acc[mt][2*p],     al[mt], bh[0], bh[1]);
                    MMA16816(acc[mt][2*p + 1], al[mt], bh[2], bh[3]);
                }
            }
        }
    };

    load_regs(0);
    for (int c = 0; c < 32; c++) {
        st_stage(c & 1);
        __syncthreads();
        if (c < 31) load_regs((c + 1) * 32);
        do_mma(c & 1);
    }

    const int lenb = lens[m0 >> 11];
    #pragma unroll
    for (int mt = 0; mt < 2; mt++) {
        int r = m0 + wm * 32 + mt * 16 + (lane >> 2);
        float mk0 = (((r)     & 2047) < lenb) ? 1.0f : 0.0f;
        float mk1 = (((r + 8) & 2047) < lenb) ? 1.0f : 0.0f;
        #pragma unroll
        for (int nt = 0; nt < 8; nt++) {
            int cc = wn * 64 + nt * 8 + (lane & 3) * 2;
            float2 v0, v1;
            v0.x = acc[mt][nt][0] * mk0; v0.y = acc[mt][nt][1] * mk0;
            v1.x = acc[mt][nt][2] * mk1; v1.y = acc[mt][nt][3] * mk1;
            *(float2*)(C + (size_t)r * Dk + cc)        = v0;
            *(float2*)(C + (size_t)(r + 8) * Dk + cc)  = v1;
        }
    }
}

// ---------------------------------------------------------------------------
// Flash attention via mma.sync, bf16x3 split for QK^T and P@V.
// BQ=BK=64, 4 warps (each owns 16 query rows). 1 CTA/SM (120KB smem).
// Pitches: 272B for 128-col bf16 tiles, 144B for 64-col (conflict-free ldsm).
// ---------------------------------------------------------------------------
#define AQP 272
#define APP 144
#define SM_Qh 0
#define SM_Ql 17408
#define SM_Kh 34816
#define SM_Kl 52224
#define SM_Vh 69632
#define SM_Vl 87040
#define SM_Ph 104448
#define SM_Pl 113664
#define ATTN_SMEM 122880

__global__ __launch_bounds__(128, 1) void attn_mma(
    const float* __restrict__ Q, const float* __restrict__ K,
    const float* __restrict__ V, float* __restrict__ Out,
    const int* __restrict__ lens)
{
    extern __shared__ char sm[];
    const uint32_t sb = smem_u32(sm);
    const int tid  = threadIdx.x;
    const int lane = tid & 31;
    const int warp = tid >> 5;
    const int b    = blockIdx.y;
    const int q0   = blockIdx.x * 64;
    const int len  = lens[b];

    const float qscale = 1.4426950408889634f / 11.313708498984761f;

    // ldmatrix lane address components
    const uint32_t a_row = lane & 15;
    const uint32_t a_col = (uint32_t)(lane >> 4) * 16;              // bytes
    const uint32_t b_row = (lane & 7) + ((lane >> 4) << 3);
    const uint32_t b_col = (uint32_t)((lane >> 3) & 1) * 16;        // bytes
    const uint32_t v_k   = (lane & 7) + ((lane >> 3) & 1) * 8;      // token within 16
    const uint32_t v_d   = (uint32_t)(lane >> 4) * 16;              // d-offset bytes

    // ---- load Q tile (scaled) ----
    {
        const float* Qg = Q + ((size_t)(b * Ll + q0)) * Dk;
        #pragma unroll
        for (int i = 0; i < 16; i++) {
            int f = tid + i * 128;
            int row = f >> 5, c4 = f & 31;
            float4 v = *(const float4*)(Qg + row * Dk + c4 * 4);
            v.x *= qscale; v.y *= qscale; v.z *= qscale; v.w *= qscale;
            split_store(sm + SM_Qh, sm + SM_Ql, row * AQP + c4 * 8, v);
        }
    }

    float o[16][4];
    #pragma unroll
    for (int nt = 0; nt < 16; nt++)
        #pragma unroll
        for (int j = 0; j < 4; j++) o[nt][j] = 0.0f;
    float mrow[2] = {-1e30f, -1e30f};
    float lrow[2] = {0.0f, 0.0f};

    const int kend = min(len, q0 + 64);
    __syncthreads();

    for (int j0 = 0; j0 < kend; j0 += 64) {
        // ---- load K, V tiles (split hi/lo) ----
        const float* Kg = K + ((size_t)(b * Ll + j0)) * Dk;
        const float* Vg = V + ((size_t)(b * Ll + j0)) * Dk;
        #pragma unroll
        for (int i = 0; i < 16; i++) {
            int f = tid + i * 128;
            int row = f >> 5, c4 = f & 31;
            uint32_t off = row * AQP + c4 * 8;
            split_store(sm + SM_Kh, sm + SM_Kl, off,
                        *(const float4*)(Kg + row * Dk + c4 * 4));
            split_store(sm + SM_Vh, sm + SM_Vl, off,
                        *(const float4*)(Vg + row * Dk + c4 * 4));
        }
        __syncthreads();

        // ---- S = Q K^T (16x64 per warp) ----
        float s[8][4];
        #pragma unroll
        for (int t = 0; t < 8; t++)
            #pragma unroll
            for (int j = 0; j < 4; j++) s[t][j] = 0.0f;

        #pragma unroll
        for (int ks = 0; ks < 8; ks++) {
            uint32_t ab = sb + SM_Qh + (warp * 16 + a_row) * AQP + ks * 32 + a_col;
            uint32_t ah[4], al[4];
            LDMX4(ah, ab);
            LDMX4(al, ab + (SM_Ql - SM_Qh));
            #pragma unroll
            for (int p = 0; p < 4; p++) {
                uint32_t bb = sb + SM_Kh + (p * 16 + b_row) * AQP + ks * 32 + b_col;
                uint32_t bh[4], bl[4];
                LDMX4(bh, bb);
                LDMX4(bl, bb + (SM_Kl - SM_Kh));
                MMA16816(s[2*p],     ah, bh[0], bh[1]);
                MMA16816(s[2*p + 1], ah, bh[2], bh[3]);
                MMA16816(s[2*p],     ah, bl[0], bl[1]);
                MMA16816(s[2*p + 1], ah, bl[2], bl[3]);
                MMA16816(s[2*p],     al, bh[0], bh[1]);
                MMA16816(s[2*p + 1], al, bh[2], bh[3]);
            }
        }

        // ---- mask + online softmax; P -> smem (bf16 hi/lo) ----
        #pragma unroll
        for (int h = 0; h < 2; h++) {
            const int qi = q0 + warp * 16 + (lane >> 2) + h * 8;
            float mx = -1e30f;
            #pragma unroll
            for (int t = 0; t < 8; t++) {
                int c = j0 + t * 8 + (lane & 3) * 2;
                float v0 = (c     <= qi && c     < len) ? s[t][2*h]     : -1e30f;
                float v1 = (c + 1 <= qi && c + 1 < len) ? s[t][2*h + 1] : -1e30f;
                s[t][2*h] = v0; s[t][2*h + 1] = v1;
                mx = fmaxf(mx, fmaxf(v0, v1));
            }
            mx = fmaxf(mx, __shfl_xor_sync(0xffffffffu, mx, 1));
            mx = fmaxf(mx, __shfl_xor_sync(0xffffffffu, mx, 2));
            float mnew  = fmaxf(mrow[h], mx);
            float alpha = exp2f(mrow[h] - mnew);
            float lsum  = 0.0f;
            const uint32_t prow = SM_Ph + (warp * 16 + (lane >> 2) + h * 8) * APP
                                + (lane & 3) * 4;
            #pragma unroll
            for (int t = 0; t < 8; t++) {
                float p0 = exp2f(s[t][2*h]     - mnew);
                float p1 = exp2f(s[t][2*h + 1] - mnew);
                lsum += p0 + p1;
                __nv_bfloat162 ph = __float22bfloat162_rn(make_float2(p0, p1));
                float2 pf = __bfloat1622float2(ph);
                __nv_bfloat162 pl =
                    __float22bfloat162_rn(make_float2(p0 - pf.x, p1 - pf.y));
                *(uint32_t*)(sm + prow + t * 16) = *(uint32_t*)&ph;
                *(uint32_t*)(sm + (SM_Pl - SM_Ph) + prow + t * 16) = *(uint32_t*)&pl;
            }
            lsum += __shfl_xor_sync(0xffffffffu, lsum, 1);
            lsum += __shfl_xor_sync(0xffffffffu, lsum, 2);
            lrow[h] = lrow[h] * alpha + lsum;
            mrow[h] = mnew;
            #pragma unroll
            for (int nt = 0; nt < 16; nt++) {
                o[nt][2*h]     *= alpha;
                o[nt][2*h + 1] *= alpha;
            }
        }
        __syncwarp();

        // ---- O += P @ V ----
        #pragma unroll
        for (int ks = 0; ks < 4; ks++) {
            uint32_t pb = sb + SM_Ph + (warp * 16 + a_row) * APP + ks * 32 + a_col;
            uint32_t ph[4], pl[4];
            LDMX4(ph, pb);
            LDMX4(pl, pb + (SM_Pl - SM_Ph));
            #pragma unroll
            for (int dt = 0; dt < 8; dt++) {
                uint32_t vb = sb + SM_Vh + (ks * 16 + v_k) * AQP + dt * 32 + v_d;
                uint32_t bh[4], bl[4];
                LDMX4T(bh, vb);
                LDMX4T(bl, vb + (SM_Vl - SM_Vh));
                MMA16816(o[2*dt],     ph, bh[0], bh[1]);
                MMA16816(o[2*dt + 1], ph, bh[2], bh[3]);
                MMA16816(o[2*dt],     ph, bl[0], bl[1]);
                MMA16816(o[2*dt + 1], ph, bl[2], bl[3]);
                MMA16816(o[2*dt],     pl, bh[0], bh[1]);
                MMA16816(o[2*dt + 1], pl, bh[2], bh[3]);
            }
        }
        __syncthreads();   // all warps done with K/V before overwrite
    }

    // ---- normalize + write ----
    #pragma unroll
    for (int h = 0; h < 2; h++) {
        float inv = 1.0f / lrow[h];
        int row = q0 + warp * 16 + (lane >> 2) + h * 8;
        float* og = Out + ((size_t)(b * Ll + row)) * Dk;
        #pragma unroll
        for (int dt = 0; dt < 16; dt++) {
            float2 v;
            v.x = o[dt][2*h]     * inv;
            v.y = o[dt][2*h + 1] * inv;
            *(float2*)(og + dt * 8 + (lane & 3) * 2) = v;
        }
    }
}

// ---------------------------------------------------------------------------
extern "C" void kernel_launch(void* const* d_in, const int* in_sizes, int n_in,
                              void* d_out, int out_size)
{
    const float* x    = (const float*)d_in[0];
    const float* ctx  = (const float*)d_in[1];
    const int*   lens = (const int*)  d_in[2];
    const float* Wq   = (const float*)d_in[3];
    const float* Wk   = (const float*)d_in[4];
    const float* Wv   = (const float*)d_in[5];
    float* out = (float*)d_out;
    (void)in_sizes; (void)n_in; (void)out_size;

    float *pQ, *pK, *pV;
    cudaGetSymbolAddress((void**)&pQ, g_Q);
    cudaGetSymbolAddress((void**)&pK, g_K);
    cudaGetSymbolAddress((void**)&pV, g_V);

    prep_weights<<<dim3(32, 4, 3), dim3(32, 32)>>>(Wq, Wk, Wv);

    cudaFuncSetAttribute(proj_mma,
                         cudaFuncAttributeMaxDynamicSharedMemorySize, PROJ_SMEM);
    proj_mma<<<dim3(Mtot / 128, 3), 256, PROJ_SMEM>>>(x, ctx, lens);

    cudaFuncSetAttribute(attn_mma,
                         cudaFuncAttributeMaxDynamicSharedMemorySize, ATTN_SMEM);
    attn_mma<<<dim3(Ll / 64, Bb), 128, ATTN_SMEM>>>(pQ, pK, pV, out, lens);
}

// round 5
// speedup vs baseline: 4.9672x; 1.0217x over previous
#include <cuda_runtime.h>
#include <cuda_bf16.h>
#include <cstdint>

#define Bb 16
#define Ll 2048
#define Ee 1024
#define Dk 128
#define Mtot (Bb*Ll)   // 32768

// Pre-split bf16 hi/lo planes for projected Q, K, V.
__device__ __nv_bfloat16 g_Qh[Mtot*Dk], g_Ql[Mtot*Dk];
__device__ __nv_bfloat16 g_Kh[Mtot*Dk], g_Kl[Mtot*Dk];
__device__ __nv_bfloat16 g_Vh[Mtot*Dk], g_Vl[Mtot*Dk];
// g_Wt layout: [mat(3)][hi/lo(2)][N=128][K=1024] bf16 (B column-major)
__device__ __nv_bfloat16 g_Wt[3 * 2 * 128 * 1024];

__device__ __forceinline__ uint32_t smem_u32(const void* p) {
    uint32_t a;
    asm("{ .reg .u64 t; cvta.to.shared.u64 t, %1; cvt.u32.u64 %0, t; }"
        : "=r"(a) : "l"(p));
    return a;
}

#define LDMX4(r, addr) \
    asm volatile("ldmatrix.sync.aligned.m8n8.x4.shared.b16 {%0,%1,%2,%3}, [%4];" \
        : "=r"((r)[0]), "=r"((r)[1]), "=r"((r)[2]), "=r"((r)[3]) : "r"(addr))

#define LDMX4T(r, addr) \
    asm volatile("ldmatrix.sync.aligned.m8n8.x4.trans.shared.b16 {%0,%1,%2,%3}, [%4];" \
        : "=r"((r)[0]), "=r"((r)[1]), "=r"((r)[2]), "=r"((r)[3]) : "r"(addr))

#define MMA16816(d, a, b0, b1) \
    asm volatile("mma.sync.aligned.m16n8k16.row.col.f32.bf16.bf16.f32 " \
        "{%0,%1,%2,%3}, {%4,%5,%6,%7}, {%8,%9}, {%0,%1,%2,%3};" \
        : "+f"((d)[0]), "+f"((d)[1]), "+f"((d)[2]), "+f"((d)[3]) \
        : "r"((a)[0]), "r"((a)[1]), "r"((a)[2]), "r"((a)[3]), "r"(b0), "r"(b1))

#define CP_COMMIT asm volatile("cp.async.commit_group;")
#define CP_WAIT(N) asm volatile("cp.async.wait_group %0;" :: "n"(N))

__device__ __forceinline__ void cpa16(uint32_t dst, const void* src) {
    asm volatile("cp.async.cg.shared.global [%0], [%1], 16;"
                 :: "r"(dst), "l"(src));
}

// fp32x4 -> bf16 hi/lo split, 8B stores (smem)
__device__ __forceinline__ void split_store(char* hi, char* lo, uint32_t off, float4 v) {
    __nv_bfloat162 h0 = __float22bfloat162_rn(make_float2(v.x, v.y));
    __nv_bfloat162 h1 = __float22bfloat162_rn(make_float2(v.z, v.w));
    float2 f0 = __bfloat1622float2(h0), f1 = __bfloat1622float2(h1);
    __nv_bfloat162 l0 = __float22bfloat162_rn(make_float2(v.x - f0.x, v.y - f0.y));
    __nv_bfloat162 l1 = __float22bfloat162_rn(make_float2(v.z - f1.x, v.w - f1.y));
    uint2 hv, lv;
    hv.x = *(uint32_t*)&h0; hv.y = *(uint32_t*)&h1;
    lv.x = *(uint32_t*)&l0; lv.y = *(uint32_t*)&l1;
    *(uint2*)(hi + off) = hv;
    *(uint2*)(lo + off) = lv;
}

// ---------------------------------------------------------------------------
// Weight prep: W[1024,128] fp32 -> Wt_hi[n][k], Wt_lo[n][k] bf16 (transposed)
// ---------------------------------------------------------------------------
__global__ void prep_weights(const float* __restrict__ Wq,
                             const float* __restrict__ Wk,
                             const float* __restrict__ Wv)
{
    __shared__ float t[32][33];
    const int mat = blockIdx.z;
    const float* W = (mat == 0) ? Wq : (mat == 1) ? Wk : Wv;
    const int k0 = blockIdx.x * 32, n0 = blockIdx.y * 32;
    const int tx = threadIdx.x, ty = threadIdx.y;
    t[ty][tx] = W[(size_t)(k0 + ty) * Dk + n0 + tx];
    __syncthreads();
    float v = t[tx][ty];
    __nv_bfloat16 hi = __float2bfloat16(v);
    float lo = v - __bfloat162float(hi);
    __nv_bfloat16* dst = g_Wt + (size_t)mat * 262144;
    size_t o = (size_t)(n0 + ty) * Ee + k0 + tx;
    dst[o] = hi;
    dst[131072 + o] = __float2bfloat16(lo);
}

// ---------------------------------------------------------------------------
// Projection GEMM via mma.sync (bf16x3 split) -> pre-split bf16 hi/lo output.
// ---------------------------------------------------------------------------
#define PROJ_SMEM (2 * 40960)

__global__ __launch_bounds__(256, 1) void proj_mma(
    const float* __restrict__ x, const float* __restrict__ ctx,
    const int* __restrict__ lens)
{
    extern __shared__ char smraw[];
    const int tid  = threadIdx.x;
    const int lane = tid & 31;
    const int wid  = tid >> 5;
    const int wm   = wid >> 1;
    const int wn   = wid & 1;
    const int mat  = blockIdx.y;
    const int m0   = blockIdx.x * 128;
    const float* A = (mat == 2) ? x : ctx;
    __nv_bfloat16* Ch = (mat == 0) ? g_Qh : (mat == 1) ? g_Kh : g_Vh;
    __nv_bfloat16* Cl = (mat == 0) ? g_Ql : (mat == 1) ? g_Kl : g_Vl;
    const __nv_bfloat16* Wh = g_Wt + (size_t)mat * 262144;
    const __nv_bfloat16* Wl = Wh + 131072;

    const uint32_t sbase = smem_u32(smraw);

    float acc[2][8][4];
    #pragma unroll
    for (int mt = 0; mt < 2; mt++)
        #pragma unroll
        for (int nt = 0; nt < 8; nt++)
            #pragma unroll
            for (int j = 0; j < 4; j++) acc[mt][nt][j] = 0.0f;

    const uint32_t a_row  = (uint32_t)(lane & 15);
    const uint32_t a_col2 = (uint32_t)((lane >> 4) << 3) * 2;
    const uint32_t b_row  = (uint32_t)((lane & 7) + ((lane >> 4) << 3));
    const uint32_t b_col2 = (uint32_t)(((lane >> 3) & 1) << 3) * 2;

    float4 ar[4];
    uint4  wr[4];

    auto load_regs = [&](int k0) {
        #pragma unroll
        for (int i = 0; i < 4; i++) {
            int f = tid + i * 256;
            int row = f >> 3, c4 = f & 7;
            ar[i] = *(const float4*)(A + (size_t)(m0 + row) * Ee + k0 + c4 * 4);
        }
        #pragma unroll
        for (int i = 0; i < 2; i++) {
            int f = tid + i * 256;
            int row = f >> 2, q = f & 3;
            wr[i]     = *(const uint4*)(Wh + (size_t)row * Ee + k0 + q * 8);
            wr[i + 2] = *(const uint4*)(Wl + (size_t)row * Ee + k0 + q * 8);
        }
    };

    auto st_stage = [&](int buf) {
        char* tb = smraw + buf * 40960;
        #pragma unroll
        for (int i = 0; i < 4; i++) {
            int f = tid + i * 256;
            int row = f >> 3, c4 = f & 7;
            split_store(tb, tb + 10240, row * 80 + c4 * 8, ar[i]);
        }
        #pragma unroll
        for (int i = 0; i < 2; i++) {
            int f = tid + i * 256;
            int row = f >> 2, q = f & 3;
            uint32_t off = row * 80 + q * 16;
            *(uint4*)(tb + 20480 + off) = wr[i];
            *(uint4*)(tb + 30720 + off) = wr[i + 2];
        }
    };

    auto do_mma = [&](int buf) {
        const uint32_t st = sbase + buf * 40960;
        #pragma unroll
        for (int ks = 0; ks < 2; ks++) {
            const uint32_t kk2 = ks * 32;
            uint32_t ah[2][4], al[2][4];
            #pragma unroll
            for (int mt = 0; mt < 2; mt++) {
                uint32_t r = wm * 32 + mt * 16 + a_row;
                uint32_t addr = st + r * 80 + kk2 + a_col2;
                LDMX4(ah[mt], addr);
                LDMX4(al[mt], addr + 10240);
            }
            #pragma unroll
            for (int p = 0; p < 4; p++) {
                uint32_t nr = wn * 64 + p * 16 + b_row;
                uint32_t addr = st + 20480 + nr * 80 + kk2 + b_col2;
                uint32_t bh[4], bl[4];
                LDMX4(bh, addr);
                LDMX4(bl, addr + 10240);
                #pragma unroll
                for (int mt = 0; mt < 2; mt++) {
                    MMA16816(acc[mt][2*p],     ah[mt], bh[0], bh[1]);
                    MMA16816(acc[mt][2*p + 1], ah[mt], bh[2], bh[3]);
                    MMA16816(acc[mt][2*p],     ah[mt], bl[0], bl[1]);
                    MMA16816(acc[mt][2*p + 1], ah[mt], bl[2], bl[3]);
                    MMA16816(acc[mt][2*p],     al[mt], bh[0], bh[1]);
                    MMA16816(acc[mt][2*p + 1], al[mt], bh[2], bh[3]);
                }
            }
        }
    };

    load_regs(0);
    for (int c = 0; c < 32; c++) {
        st_stage(c & 1);
        __syncthreads();
        if (c < 31) load_regs((c + 1) * 32);
        do_mma(c & 1);
    }

    // Epilogue: masked hi/lo bf16 split store.
    const int lenb = lens[m0 >> 11];
    #pragma unroll
    for (int mt = 0; mt < 2; mt++) {
        int r = m0 + wm * 32 + mt * 16 + (lane >> 2);
        float mk0 = (((r)     & 2047) < lenb) ? 1.0f : 0.0f;
        float mk1 = (((r + 8) & 2047) < lenb) ? 1.0f : 0.0f;
        #pragma unroll
        for (int nt = 0; nt < 8; nt++) {
            int cc = wn * 64 + nt * 8 + (lane & 3) * 2;
            float2 v0 = make_float2(acc[mt][nt][0] * mk0, acc[mt][nt][1] * mk0);
            float2 v1 = make_float2(acc[mt][nt][2] * mk1, acc[mt][nt][3] * mk1);
            __nv_bfloat162 h0 = __float22bfloat162_rn(v0);
            __nv_bfloat162 h1 = __float22bfloat162_rn(v1);
            float2 f0 = __bfloat1622float2(h0), f1 = __bfloat1622float2(h1);
            __nv_bfloat162 l0 =
                __float22bfloat162_rn(make_float2(v0.x - f0.x, v0.y - f0.y));
            __nv_bfloat162 l1 =
                __float22bfloat162_rn(make_float2(v1.x - f1.x, v1.y - f1.y));
            *(uint32_t*)(Ch + (size_t)r * Dk + cc)       = *(uint32_t*)&h0;
            *(uint32_t*)(Cl + (size_t)r * Dk + cc)       = *(uint32_t*)&l0;
            *(uint32_t*)(Ch + (size_t)(r + 8) * Dk + cc) = *(uint32_t*)&h1;
            *(uint32_t*)(Cl + (size_t)(r + 8) * Dk + cc) = *(uint32_t*)&l1;
        }
    }
}

// ---------------------------------------------------------------------------
// Flash attention via mma.sync, bf16x3, cp.async-pipelined.
// BQ=128, BK=64, 8 warps (16 query rows each). K double-buffered.
// ---------------------------------------------------------------------------
#define AQP 272
#define APP 144
#define SM_Qh 0
#define SM_Ql 34816
#define SM_K  69632     /* + stage*34816 + plane*17408 */
#define SM_V  139264    /* + plane*17408 */
#define SM_P  174080    /* + plane*18432 */
#define ATTN_SMEM 210944

__global__ __launch_bounds__(256, 1) void attn_mma(
    float* __restrict__ Out, const int* __restrict__ lens)
{
    extern __shared__ char sm[];
    const uint32_t sb = smem_u32(sm);
    const int tid  = threadIdx.x;
    const int lane = tid & 31;
    const int warp = tid >> 5;
    const int b    = blockIdx.y;
    const int q0   = blockIdx.x * 128;
    const int len  = lens[b];

    const float qsc = 1.4426950408889634f / 11.313708498984761f;

    const uint32_t a_row = lane & 15;
    const uint32_t a_col = (uint32_t)(lane >> 4) * 16;
    const uint32_t b_row = (lane & 7) + ((lane >> 4) << 3);
    const uint32_t b_col = (uint32_t)((lane >> 3) & 1) * 16;
    const uint32_t v_k   = (lane & 7) + ((lane >> 3) & 1) * 8;
    const uint32_t v_d   = (uint32_t)(lane >> 4) * 16;

    auto copy_Q = [&]() {
        #pragma unroll
        for (int i = 0; i < 8; i++) {
            int f = tid + i * 256;          // 0..2047
            int row = f >> 4, c = f & 15;
            uint32_t d = sb + SM_Qh + row * AQP + c * 16;
            size_t g = (size_t)(b * Ll + q0 + row) * Dk + c * 8;
            cpa16(d, g_Qh + g);
            cpa16(d + (SM_Ql - SM_Qh), g_Ql + g);
        }
    };
    auto copy_K = [&](int stage, int j0) {
        const uint32_t kb = sb + SM_K + stage * 34816;
        #pragma unroll
        for (int i = 0; i < 4; i++) {
            int f = tid + i * 256;          // 0..1023
            int row = f >> 4, c = f & 15;
            uint32_t d = kb + row * AQP + c * 16;
            size_t g = (size_t)(b * Ll + j0 + row) * Dk + c * 8;
            cpa16(d, g_Kh + g);
            cpa16(d + 17408, g_Kl + g);
        }
    };
    auto copy_V = [&](int j0) {
        #pragma unroll
        for (int i = 0; i < 4; i++) {
            int f = tid + i * 256;
            int row = f >> 4, c = f & 15;
            uint32_t d = sb + SM_V + row * AQP + c * 16;
            size_t g = (size_t)(b * Ll + j0 + row) * Dk + c * 8;
            cpa16(d, g_Vh + g);
            cpa16(d + 17408, g_Vl + g);
        }
    };

    float o[16][4];
    #pragma unroll
    for (int nt = 0; nt < 16; nt++)
        #pragma unroll
        for (int j = 0; j < 4; j++) o[nt][j] = 0.0f;
    float mrow[2] = {-1e30f, -1e30f};
    float lrow[2] = {0.0f, 0.0f};

    const int kend = min(len, q0 + 128);

    copy_Q();
    copy_K(0, 0);
    CP_COMMIT;
    CP_WAIT(0);
    __syncthreads();

    int cur = 0;
    for (int j0 = 0; j0 < kend; j0 += 64) {
        // prefetch V(i) — covered by QK MMAs
        copy_V(j0);
        CP_COMMIT;

        // ---- S = Q K^T (16x64 per warp) ----
        float s[8][4];
        #pragma unroll
        for (int t = 0; t < 8; t++)
            #pragma unroll
            for (int j = 0; j < 4; j++) s[t][j] = 0.0f;

        const uint32_t kbase = sb + SM_K + cur * 34816;
        #pragma unroll
        for (int ks = 0; ks < 8; ks++) {
            uint32_t ab = sb + SM_Qh + (warp * 16 + a_row) * AQP + ks * 32 + a_col;
            uint32_t ah[4], al[4];
            LDMX4(ah, ab);
            LDMX4(al, ab + (SM_Ql - SM_Qh));
            #pragma unroll
            for (int p = 0; p < 4; p++) {
                uint32_t bb = kbase + (p * 16 + b_row) * AQP + ks * 32 + b_col;
                uint32_t bh[4], bl[4];
                LDMX4(bh, bb);
                LDMX4(bl, bb + 17408);
                MMA16816(s[2*p],     ah, bh[0], bh[1]);
                MMA16816(s[2*p + 1], ah, bh[2], bh[3]);
                MMA16816(s[2*p],     ah, bl[0], bl[1]);
                MMA16816(s[2*p + 1], ah, bl[2], bl[3]);
                MMA16816(s[2*p],     al, bh[0], bh[1]);
                MMA16816(s[2*p + 1], al, bh[2], bh[3]);
            }
        }

        // prefetch K(i+1) — covered by softmax + PV
        bool more = (j0 + 64 < kend);
        if (more) {
            copy_K(cur ^ 1, j0 + 64);
            CP_COMMIT;
            CP_WAIT(1);        // V(i) complete; K(i+1) may fly
        } else {
            CP_WAIT(0);
        }
        __syncthreads();       // V visible to all warps

        // ---- mask + online softmax; P -> smem (bf16 hi/lo) ----
        #pragma unroll
        for (int h = 0; h < 2; h++) {
            const int qi = q0 + warp * 16 + (lane >> 2) + h * 8;
            float mx = -1e30f;
            #pragma unroll
            for (int t = 0; t < 8; t++) {
                int c = j0 + t * 8 + (lane & 3) * 2;
                float v0 = (c     <= qi && c     < len) ? s[t][2*h] * qsc : -1e30f;
                float v1 = (c + 1 <= qi && c + 1 < len) ? s[t][2*h+1] * qsc : -1e30f;
                s[t][2*h] = v0; s[t][2*h + 1] = v1;
                mx = fmaxf(mx, fmaxf(v0, v1));
            }
            mx = fmaxf(mx, __shfl_xor_sync(0xffffffffu, mx, 1));
            mx = fmaxf(mx, __shfl_xor_sync(0xffffffffu, mx, 2));
            float mnew  = fmaxf(mrow[h], mx);
            float alpha = exp2f(mrow[h] - mnew);
            float lsum  = 0.0f;
            const uint32_t prow = SM_P + (warp * 16 + (lane >> 2) + h * 8) * APP
                                + (lane & 3) * 4;
            #pragma unroll
            for (int t = 0; t < 8; t++) {
                float p0 = exp2f(s[t][2*h]     - mnew);
                float p1 = exp2f(s[t][2*h + 1] - mnew);
                lsum += p0 + p1;
                __nv_bfloat162 ph = __float22bfloat162_rn(make_float2(p0, p1));
                float2 pf = __bfloat1622float2(ph);
                __nv_bfloat162 pl =
                    __float22bfloat162_rn(make_float2(p0 - pf.x, p1 - pf.y));
                *(uint32_t*)(sm + prow + t * 16) = *(uint32_t*)&ph;
                *(uint32_t*)(sm + 18432 + prow + t * 16) = *(uint32_t*)&pl;
            }
            lsum += __shfl_xor_sync(0xffffffffu, lsum, 1);
            lsum += __shfl_xor_sync(0xffffffffu, lsum, 2);
            lrow[h] = lrow[h] * alpha + lsum;
            mrow[h] = mnew;
            #pragma unroll
            for (int nt = 0; nt < 16; nt++) {
                o[nt][2*h]     *= alpha;
                o[nt][2*h + 1] *= alpha;
            }
        }
        __syncwarp();

        // ---- O += P @ V ----
        #pragma unroll
        for (int ks = 0; ks < 4; ks++) {
            uint32_t pb = sb + SM_P + (warp * 16 + a_row) * APP + ks * 32 + a_col;
            uint32_t ph[4], pl[4];
            LDMX4(ph, pb);
            LDMX4(pl, pb + 18432);
            #pragma unroll
            for (int dt = 0; dt < 8; dt++) {
                uint32_t vb = sb + SM_V + (ks * 16 + v_k) * AQP + dt * 32 + v_d;
                uint32_t bh[4], bl[4];
                LDMX4T(bh, vb);
                LDMX4T(bl, vb + 17408);
                MMA16816(o[2*dt],     ph, bh[0], bh[1]);
                MMA16816(o[2*dt + 1], ph, bh[2], bh[3]);
                MMA16816(o[2*dt],     ph, bl[0], bl[1]);
                MMA16816(o[2*dt + 1], ph, bl[2], bl[3]);
                MMA16816(o[2*dt],     pl, bh[0], bh[1]);
                MMA16816(o[2*dt + 1], pl, bh[2], bh[3]);
            }
        }
        CP_WAIT(0);            // K(i+1) landed
        __syncthreads();       // V/K buffers free for next iter
        cur ^= 1;
    }

    // ---- normalize + write ----
    #pragma unroll
    for (int h = 0; h < 2; h++) {
        float inv = 1.0f / lrow[h];
        int row = q0 + warp * 16 + (lane >> 2) + h * 8;
        float* og = Out + ((size_t)(b * Ll + row)) * Dk;
        #pragma unroll
        for (int dt = 0; dt < 16; dt++) {
            float2 v;
            v.x = o[dt][2*h]     * inv;
            v.y = o[dt][2*h + 1] * inv;
            *(float2*)(og + dt * 8 + (lane & 3) * 2) = v;
        }
    }
}

// ---------------------------------------------------------------------------
extern "C" void kernel_launch(void* const* d_in, const int* in_sizes, int n_in,
                              void* d_out, int out_size)
{
    const float* x    = (const float*)d_in[0];
    const float* ctx  = (const float*)d_in[1];
    const int*   lens = (const int*)  d_in[2];
    const float* Wq   = (const float*)d_in[3];
    const float* Wk   = (const float*)d_in[4];
    const float* Wv   = (const float*)d_in[5];
    float* out = (float*)d_out;
    (void)in_sizes; (void)n_in; (void)out_size;

    prep_weights<<<dim3(32, 4, 3), dim3(32, 32)>>>(Wq, Wk, Wv);

    cudaFuncSetAttribute(proj_mma,
                         cudaFuncAttributeMaxDynamicSharedMemorySize, PROJ_SMEM);
    proj_mma<<<dim3(Mtot / 128, 3), 256, PROJ_SMEM>>>(x, ctx, lens);

    cudaFuncSetAttribute(attn_mma,
                         cudaFuncAttributeMaxDynamicSharedMemorySize, ATTN_SMEM);
    attn_mma<<<dim3(Ll / 128, Bb), 256, ATTN_SMEM>>>(out, lens);
}

// round 6
// speedup vs baseline: 5.9918x; 1.2063x over previous
#include <cuda_runtime.h>
#include <cuda_fp16.h>
#include <cstdint>

#define Bb 16
#define Ll 2048
#define Ee 1024
#define Dk 128
#define Mtot (Bb*Ll)   // 32768

// fp16 planes: Q single (qscale folded), K/V hi+lo.
__device__ __half g_Qf[Mtot*Dk];
__device__ __half g_Kh[Mtot*Dk], g_Kl[Mtot*Dk];
__device__ __half g_Vh[Mtot*Dk], g_Vl[Mtot*Dk];
// Weights: [mat(3)][hi/lo(2)][N=128][K=1024] fp16, pre-scaled by 32.
__device__ __half g_Wt[3 * 2 * 128 * 1024];

#define QSCALE 0.12751743f   /* log2(e)/sqrt(128) */

__device__ __forceinline__ uint32_t smem_u32(const void* p) {
    uint32_t a;
    asm("{ .reg .u64 t; cvta.to.shared.u64 t, %1; cvt.u32.u64 %0, t; }"
        : "=r"(a) : "l"(p));
    return a;
}

#define LDMX4(r, addr) \
    asm volatile("ldmatrix.sync.aligned.m8n8.x4.shared.b16 {%0,%1,%2,%3}, [%4];" \
        : "=r"((r)[0]), "=r"((r)[1]), "=r"((r)[2]), "=r"((r)[3]) : "r"(addr))

#define LDMX4T(r, addr) \
    asm volatile("ldmatrix.sync.aligned.m8n8.x4.trans.shared.b16 {%0,%1,%2,%3}, [%4];" \
        : "=r"((r)[0]), "=r"((r)[1]), "=r"((r)[2]), "=r"((r)[3]) : "r"(addr))

#define MMAF16(d, a, b0, b1) \
    asm volatile("mma.sync.aligned.m16n8k16.row.col.f32.f16.f16.f32 " \
        "{%0,%1,%2,%3}, {%4,%5,%6,%7}, {%8,%9}, {%0,%1,%2,%3};" \
        : "+f"((d)[0]), "+f"((d)[1]), "+f"((d)[2]), "+f"((d)[3]) \
        : "r"((a)[0]), "r"((a)[1]), "r"((a)[2]), "r"((a)[3]), "r"(b0), "r"(b1))

#define CP_COMMIT asm volatile("cp.async.commit_group;")
#define CP_WAIT(N) asm volatile("cp.async.wait_group %0;" :: "n"(N))

__device__ __forceinline__ void cpa16(uint32_t dst, const void* src) {
    asm volatile("cp.async.cg.shared.global [%0], [%1], 16;"
                 :: "r"(dst), "l"(src));
}

__device__ __forceinline__ uint32_t pack_h2(float x, float y) {
    __half2 h = __floats2half2_rn(x, y);
    return *(uint32_t*)&h;
}

// ---------------------------------------------------------------------------
// Weight prep: W[1024,128] fp32 -> 32*W as fp16 hi/lo, transposed [n][k].
// ---------------------------------------------------------------------------
__global__ void prep_weights(const float* __restrict__ Wq,
                             const float* __restrict__ Wk,
                             const float* __restrict__ Wv)
{
    __shared__ float t[32][33];
    const int mat = blockIdx.z;
    const float* W = (mat == 0) ? Wq : (mat == 1) ? Wk : Wv;
    const int k0 = blockIdx.x * 32, n0 = blockIdx.y * 32;
    const int tx = threadIdx.x, ty = threadIdx.y;
    t[ty][tx] = W[(size_t)(k0 + ty) * Dk + n0 + tx];
    __syncthreads();
    float v = t[tx][ty] * 32.0f;
    __half hi = __float2half_rn(v);
    float lo = v - __half2float(hi);
    __half* dst = g_Wt + (size_t)mat * 262144;
    size_t o = (size_t)(n0 + ty) * Ee + k0 + tx;
    dst[o] = hi;
    dst[131072 + o] = __float2half_rn(lo);
}

// ---------------------------------------------------------------------------
// Projection GEMM: A single fp16, W hi/lo fp16 -> 2 MMAs per tile.
// Stage: A 128x32 fp16 (pitch 80B) | Wh | Wl  -> 30720 B; double buffered.
// ---------------------------------------------------------------------------
#define PROJ_SMEM (2 * 30720)

__global__ __launch_bounds__(256, 1) void proj_mma(
    const float* __restrict__ x, const float* __restrict__ ctx,
    const int* __restrict__ lens)
{
    extern __shared__ char smraw[];
    const int tid  = threadIdx.x;
    const int lane = tid & 31;
    const int wid  = tid >> 5;
    const int wm   = wid >> 1;
    const int wn   = wid & 1;
    const int mat  = blockIdx.y;
    const int m0   = blockIdx.x * 128;
    const float* A = (mat == 2) ? x : ctx;
    __half* Ch = (mat == 0) ? g_Qf : (mat == 1) ? g_Kh : g_Vh;
    __half* Cl = (mat == 1) ? g_Kl : g_Vl;      // unused for mat 0
    const __half* Wh = g_Wt + (size_t)mat * 262144;
    const __half* Wl = Wh + 131072;

    const uint32_t sbase = smem_u32(smraw);

    float acc[2][8][4];
    #pragma unroll
    for (int mt = 0; mt < 2; mt++)
        #pragma unroll
        for (int nt = 0; nt < 8; nt++)
            #pragma unroll
            for (int j = 0; j < 4; j++) acc[mt][nt][j] = 0.0f;

    const uint32_t a_row  = (uint32_t)(lane & 15);
    const uint32_t a_col2 = (uint32_t)((lane >> 4) << 3) * 2;
    const uint32_t b_row  = (uint32_t)((lane & 7) + ((lane >> 4) << 3));
    const uint32_t b_col2 = (uint32_t)(((lane >> 3) & 1) << 3) * 2;

    float4 ar[4];
    uint4  wr[4];

    auto load_regs = [&](int k0) {
        #pragma unroll
        for (int i = 0; i < 4; i++) {
            int f = tid + i * 256;
            int row = f >> 3, c4 = f & 7;
            ar[i] = *(const float4*)(A + (size_t)(m0 + row) * Ee + k0 + c4 * 4);
        }
        #pragma unroll
        for (int i = 0; i < 2; i++) {
            int f = tid + i * 256;
            int row = f >> 2, q = f & 3;
            wr[i]     = *(const uint4*)(Wh + (size_t)row * Ee + k0 + q * 8);
            wr[i + 2] = *(const uint4*)(Wl + (size_t)row * Ee + k0 + q * 8);
        }
    };

    auto st_stage = [&](int buf) {
        char* tb = smraw + buf * 30720;
        #pragma unroll
        for (int i = 0; i < 4; i++) {
            int f = tid + i * 256;
            int row = f >> 3, c4 = f & 7;
            float4 v = ar[i];
            uint2 hv;
            hv.x = pack_h2(v.x, v.y);
            hv.y = pack_h2(v.z, v.w);
            *(uint2*)(tb + row * 80 + c4 * 8) = hv;
        }
        #pragma unroll
        for (int i = 0; i < 2; i++) {
            int f = tid + i * 256;
            int row = f >> 2, q = f & 3;
            uint32_t off = row * 80 + q * 16;
            *(uint4*)(tb + 10240 + off) = wr[i];
            *(uint4*)(tb + 20480 + off) = wr[i + 2];
        }
    };

    auto do_mma = [&](int buf) {
        const uint32_t st = sbase + buf * 30720;
        #pragma unroll
        for (int ks = 0; ks < 2; ks++) {
            const uint32_t kk2 = ks * 32;
            uint32_t af[2][4];
            #pragma unroll
            for (int mt = 0; mt < 2; mt++) {
                uint32_t r = wm * 32 + mt * 16 + a_row;
                LDMX4(af[mt], st + r * 80 + kk2 + a_col2);
            }
            #pragma unroll
            for (int p = 0; p < 4; p++) {
                uint32_t nr = wn * 64 + p * 16 + b_row;
                uint32_t addr = st + 10240 + nr * 80 + kk2 + b_col2;
                uint32_t bh[4], bl[4];
                LDMX4(bh, addr);
                LDMX4(bl, addr + 10240);
                #pragma unroll
                for (int mt = 0; mt < 2; mt++) {
                    MMAF16(acc[mt][2*p],     af[mt], bh[0], bh[1]);
                    MMAF16(acc[mt][2*p + 1], af[mt], bh[2], bh[3]);
                    MMAF16(acc[mt][2*p],     af[mt], bl[0], bl[1]);
                    MMAF16(acc[mt][2*p + 1], af[mt], bl[2], bl[3]);
                }
            }
        }
    };

    load_regs(0);
    for (int c = 0; c < 32; c++) {
        st_stage(c & 1);
        __syncthreads();
        if (c < 31) load_regs((c + 1) * 32);
        do_mma(c & 1);
    }

    // Epilogue: /32 (weight prescale), mask, then fp16 plane stores.
    const int lenb = lens[m0 >> 11];
    const float sc = (mat == 0) ? (QSCALE / 32.0f) : (1.0f / 32.0f);
    #pragma unroll
    for (int mt = 0; mt < 2; mt++) {
        int r = m0 + wm * 32 + mt * 16 + (lane >> 2);
        float mk0 = ((((r)     & 2047) < lenb) ? 1.0f : 0.0f) * sc;
        float mk1 = ((((r + 8) & 2047) < lenb) ? 1.0f : 0.0f) * sc;
        #pragma unroll
        for (int nt = 0; nt < 8; nt++) {
            int cc = wn * 64 + nt * 8 + (lane & 3) * 2;
            float2 v0 = make_float2(acc[mt][nt][0] * mk0, acc[mt][nt][1] * mk0);
            float2 v1 = make_float2(acc[mt][nt][2] * mk1, acc[mt][nt][3] * mk1);
            if (mat == 0) {
                *(uint32_t*)(Ch + (size_t)r * Dk + cc)       = pack_h2(v0.x, v0.y);
                *(uint32_t*)(Ch + (size_t)(r + 8) * Dk + cc) = pack_h2(v1.x, v1.y);
            } else {
                uint32_t h0 = pack_h2(v0.x, v0.y);
                uint32_t h1 = pack_h2(v1.x, v1.y);
                __half2 h0h = *(__half2*)&h0, h1h = *(__half2*)&h1;
                float2 f0 = __half22float2(h0h), f1 = __half22float2(h1h);
                *(uint32_t*)(Ch + (size_t)r * Dk + cc)       = h0;
                *(uint32_t*)(Cl + (size_t)r * Dk + cc)       =
                    pack_h2(v0.x - f0.x, v0.y - f0.y);
                *(uint32_t*)(Ch + (size_t)(r + 8) * Dk + cc) = h1;
                *(uint32_t*)(Cl + (size_t)(r + 8) * Dk + cc) =
                    pack_h2(v1.x - f1.x, v1.y - f1.y);
            }
        }
    }
}

// ---------------------------------------------------------------------------
// Flash attention: Q/P single fp16, K/V hi+lo fp16; cp.async pipelined.
// BQ=128, BK=64, 8 warps. K double-buffered.
// ---------------------------------------------------------------------------
#define AQP 272
#define APP 144
#define SM_Qf 0
#define SM_K  34816     /* + stage*34816 + plane*17408 */
#define SM_V  104448    /* + plane*17408 */
#define SM_P  139264
#define ATTN_SMEM 157696

__global__ __launch_bounds__(256, 1) void attn_mma(
    float* __restrict__ Out, const int* __restrict__ lens)
{
    extern __shared__ char sm[];
    const uint32_t sb = smem_u32(sm);
    const int tid  = threadIdx.x;
    const int lane = tid & 31;
    const int warp = tid >> 5;
    const int b    = blockIdx.y;
    const int q0   = blockIdx.x * 128;
    const int len  = lens[b];

    const uint32_t a_row = lane & 15;
    const uint32_t a_col = (uint32_t)(lane >> 4) * 16;
    const uint32_t b_row = (lane & 7) + ((lane >> 4) << 3);
    const uint32_t b_col = (uint32_t)((lane >> 3) & 1) * 16;
    const uint32_t v_k   = (lane & 7) + ((lane >> 3) & 1) * 8;
    const uint32_t v_d   = (uint32_t)(lane >> 4) * 16;

    auto copy_Q = [&]() {
        #pragma unroll
        for (int i = 0; i < 8; i++) {
            int f = tid + i * 256;          // 0..2047
            int row = f >> 4, c = f & 15;
            cpa16(sb + SM_Qf + row * AQP + c * 16,
                  g_Qf + (size_t)(b * Ll + q0 + row) * Dk + c * 8);
        }
    };
    auto copy_K = [&](int stage, int j0) {
        const uint32_t kb = sb + SM_K + stage * 34816;
        #pragma unroll
        for (int i = 0; i < 4; i++) {
            int f = tid + i * 256;          // 0..1023
            int row = f >> 4, c = f & 15;
            uint32_t d = kb + row * AQP + c * 16;
            size_t g = (size_t)(b * Ll + j0 + row) * Dk + c * 8;
            cpa16(d, g_Kh + g);
            cpa16(d + 17408, g_Kl + g);
        }
    };
    auto copy_V = [&](int j0) {
        #pragma unroll
        for (int i = 0; i < 4; i++) {
            int f = tid + i * 256;
            int row = f >> 4, c = f & 15;
            uint32_t d = sb + SM_V + row * AQP + c * 16;
            size_t g = (size_t)(b * Ll + j0 + row) * Dk + c * 8;
            cpa16(d, g_Vh + g);
            cpa16(d + 17408, g_Vl + g);
        }
    };

    float o[16][4];
    #pragma unroll
    for (int nt = 0; nt < 16; nt++)
        #pragma unroll
        for (int j = 0; j < 4; j++) o[nt][j] = 0.0f;
    float mrow[2] = {-1e30f, -1e30f};
    float lrow[2] = {0.0f, 0.0f};

    const int kend = min(len, q0 + 128);

    copy_Q();
    copy_K(0, 0);
    CP_COMMIT;
    CP_WAIT(0);
    __syncthreads();

    int cur = 0;
    for (int j0 = 0; j0 < kend; j0 += 64) {
        // prefetch V(i) — covered by QK MMAs
        copy_V(j0);
        CP_COMMIT;

        // ---- S = Q K^T (16x64 per warp), logits already in log2 domain ----
        float s[8][4];
        #pragma unroll
        for (int t = 0; t < 8; t++)
            #pragma unroll
            for (int j = 0; j < 4; j++) s[t][j] = 0.0f;

        const uint32_t kbase = sb + SM_K + cur * 34816;
        #pragma unroll
        for (int ks = 0; ks < 8; ks++) {
            uint32_t qf[4];
            LDMX4(qf, sb + SM_Qf + (warp * 16 + a_row) * AQP + ks * 32 + a_col);
            #pragma unroll
            for (int p = 0; p < 4; p++) {
                uint32_t bb = kbase + (p * 16 + b_row) * AQP + ks * 32 + b_col;
                uint32_t bh[4], bl[4];
                LDMX4(bh, bb);
                LDMX4(bl, bb + 17408);
                MMAF16(s[2*p],     qf, bh[0], bh[1]);
                MMAF16(s[2*p + 1], qf, bh[2], bh[3]);
                MMAF16(s[2*p],     qf, bl[0], bl[1]);
                MMAF16(s[2*p + 1], qf, bl[2], bl[3]);
            }
        }

        // prefetch K(i+1) — covered by softmax + PV
        bool more = (j0 + 64 < kend);
        if (more) {
            copy_K(cur ^ 1, j0 + 64);
            CP_COMMIT;
            CP_WAIT(1);
        } else {
            CP_WAIT(0);
        }
        __syncthreads();

        // ---- mask + online softmax; P -> smem fp16 ----
        #pragma unroll
        for (int h = 0; h < 2; h++) {
            const int qi = q0 + warp * 16 + (lane >> 2) + h * 8;
            float mx = -1e30f;
            #pragma unroll
            for (int t = 0; t < 8; t++) {
                int c = j0 + t * 8 + (lane & 3) * 2;
                float v0 = (c     <= qi && c     < len) ? s[t][2*h]     : -1e30f;
                float v1 = (c + 1 <= qi && c + 1 < len) ? s[t][2*h + 1] : -1e30f;
                s[t][2*h] = v0; s[t][2*h + 1] = v1;
                mx = fmaxf(mx, fmaxf(v0, v1));
            }
            mx = fmaxf(mx, __shfl_xor_sync(0xffffffffu, mx, 1));
            mx = fmaxf(mx, __shfl_xor_sync(0xffffffffu, mx, 2));
            float mnew  = fmaxf(mrow[h], mx);
            float alpha = exp2f(mrow[h] - mnew);
            float lsum  = 0.0f;
            const uint32_t prow = SM_P + (warp * 16 + (lane >> 2) + h * 8) * APP
                                + (lane & 3) * 4;
            #pragma unroll
            for (int t = 0; t < 8; t++) {
                float p0 = exp2f(s[t][2*h]     - mnew);
                float p1 = exp2f(s[t][2*h + 1] - mnew);
                lsum += p0 + p1;
                *(uint32_t*)(sm + prow + t * 16) = pack_h2(p0, p1);
            }
            lsum += __shfl_xor_sync(0xffffffffu, lsum, 1);
            lsum += __shfl_xor_sync(0xffffffffu, lsum, 2);
            lrow[h] = lrow[h] * alpha + lsum;
            mrow[h] = mnew;
            #pragma unroll
            for (int nt = 0; nt < 16; nt++) {
                o[nt][2*h]     *= alpha;
                o[nt][2*h + 1] *= alpha;
            }
        }
        __syncwarp();

        // ---- O += P @ V ----
        #pragma unroll
        for (int ks = 0; ks < 4; ks++) {
            uint32_t pf[4];
            LDMX4(pf, sb + SM_P + (warp * 16 + a_row) * APP + ks * 32 + a_col);
            #pragma unroll
            for (int dt = 0; dt < 8; dt++) {
                uint32_t vb = sb + SM_V + (ks * 16 + v_k) * AQP + dt * 32 + v_d;
                uint32_t bh[4], bl[4];
                LDMX4T(bh, vb);
                LDMX4T(bl, vb + 17408);
                MMAF16(o[2*dt],     pf, bh[0], bh[1]);
                MMAF16(o[2*dt + 1], pf, bh[2], bh[3]);
                MMAF16(o[2*dt],     pf, bl[0], bl[1]);
                MMAF16(o[2*dt + 1], pf, bl[2], bl[3]);
            }
        }
        CP_WAIT(0);
        __syncthreads();
        cur ^= 1;
    }

    // ---- normalize + write ----
    #pragma unroll
    for (int h = 0; h < 2; h++) {
        float inv = 1.0f / lrow[h];
        int row = q0 + warp * 16 + (lane >> 2) + h * 8;
        float* og = Out + ((size_t)(b * Ll + row)) * Dk;
        #pragma unroll
        for (int dt = 0; dt < 16; dt++) {
            float2 v;
            v.x = o[dt][2*h]     * inv;
            v.y = o[dt][2*h + 1] * inv;
            *(float2*)(og + dt * 8 + (lane & 3) * 2) = v;
        }
    }
}

// ---------------------------------------------------------------------------
extern "C" void kernel_launch(void* const* d_in, const int* in_sizes, int n_in,
                              void* d_out, int out_size)
{
    const float* x    = (const float*)d_in[0];
    const float* ctx  = (const float*)d_in[1];
    const int*   lens = (const int*)  d_in[2];
    const float* Wq   = (const float*)d_in[3];
    const float* Wk   = (const float*)d_in[4];
    const float* Wv   = (const float*)d_in[5];
    float* out = (float*)d_out;
    (void)in_sizes; (void)n_in; (void)out_size;

    prep_weights<<<dim3(32, 4, 3), dim3(32, 32)>>>(Wq, Wk, Wv);

    cudaFuncSetAttribute(proj_mma,
                         cudaFuncAttributeMaxDynamicSharedMemorySize, PROJ_SMEM);
    proj_mma<<<dim3(Mtot / 128, 3), 256, PROJ_SMEM>>>(x, ctx, lens);

    cudaFuncSetAttribute(attn_mma,
                         cudaFuncAttributeMaxDynamicSharedMemorySize, ATTN_SMEM);
    attn_mma<<<dim3(Ll / 128, Bb), 256, ATTN_SMEM>>>(out, lens);
}

// round 7
// speedup vs baseline: 8.4589x; 1.4117x over previous
#include <cuda_runtime.h>
#include <cuda_fp16.h>
#include <cstdint>

#define Bb 16
#define Ll 2048
#define Ee 1024
#define Dk 128
#define Mtot (Bb*Ll)   // 32768

// Single fp16 planes: Q (qscale folded), K, V.
__device__ __half g_Qf[Mtot*Dk];
__device__ __half g_Kf[Mtot*Dk];
__device__ __half g_Vf[Mtot*Dk];
// Weights: [mat(3)][N=128][K=1024] fp16, pre-scaled by 32 (epilogue /32).
__device__ __half g_Wt[3 * 128 * 1024];

#define QSCALE 0.12751743f   /* log2(e)/sqrt(128) */

__device__ __forceinline__ uint32_t smem_u32(const void* p) {
    uint32_t a;
    asm("{ .reg .u64 t; cvta.to.shared.u64 t, %1; cvt.u32.u64 %0, t; }"
        : "=r"(a) : "l"(p));
    return a;
}

#define LDMX4(r, addr) \
    asm volatile("ldmatrix.sync.aligned.m8n8.x4.shared.b16 {%0,%1,%2,%3}, [%4];" \
        : "=r"((r)[0]), "=r"((r)[1]), "=r"((r)[2]), "=r"((r)[3]) : "r"(addr))

#define LDMX4T(r, addr) \
    asm volatile("ldmatrix.sync.aligned.m8n8.x4.trans.shared.b16 {%0,%1,%2,%3}, [%4];" \
        : "=r"((r)[0]), "=r"((r)[1]), "=r"((r)[2]), "=r"((r)[3]) : "r"(addr))

#define MMAF16(d, a, b0, b1) \
    asm volatile("mma.sync.aligned.m16n8k16.row.col.f32.f16.f16.f32 " \
        "{%0,%1,%2,%3}, {%4,%5,%6,%7}, {%8,%9}, {%0,%1,%2,%3};" \
        : "+f"((d)[0]), "+f"((d)[1]), "+f"((d)[2]), "+f"((d)[3]) \
        : "r"((a)[0]), "r"((a)[1]), "r"((a)[2]), "r"((a)[3]), "r"(b0), "r"(b1))

#define CP_COMMIT asm volatile("cp.async.commit_group;")
#define CP_WAIT(N) asm volatile("cp.async.wait_group %0;" :: "n"(N))

__device__ __forceinline__ void cpa16(uint32_t dst, const void* src) {
    asm volatile("cp.async.cg.shared.global [%0], [%1], 16;"
                 :: "r"(dst), "l"(src));
}

__device__ __forceinline__ uint32_t pack_h2(float x, float y) {
    __half2 h = __floats2half2_rn(x, y);
    return *(uint32_t*)&h;
}

// ---------------------------------------------------------------------------
// Weight prep: W[1024,128] fp32 -> 32*W fp16, transposed [n][k].
// ---------------------------------------------------------------------------
__global__ void prep_weights(const float* __restrict__ Wq,
                             const float* __restrict__ Wk,
                             const float* __restrict__ Wv)
{
    __shared__ float t[32][33];
    const int mat = blockIdx.z;
    const float* W = (mat == 0) ? Wq : (mat == 1) ? Wk : Wv;
    const int k0 = blockIdx.x * 32, n0 = blockIdx.y * 32;
    const int tx = threadIdx.x, ty = threadIdx.y;
    t[ty][tx] = W[(size_t)(k0 + ty) * Dk + n0 + tx];
    __syncthreads();
    g_Wt[(size_t)mat * 131072 + (size_t)(n0 + ty) * Ee + k0 + tx] =
        __float2half_rn(t[tx][ty] * 32.0f);
}

// ---------------------------------------------------------------------------
// Projection GEMM: A fp16 x W fp16, 1 MMA per 16x8x16 tile.
// Stage: A 128x32 fp16 (pitch 80B, 10240B) | W (10240B); double buffered.
// ---------------------------------------------------------------------------
#define PROJ_SMEM (2 * 20480)

__global__ __launch_bounds__(256, 1) void proj_mma(
    const float* __restrict__ x, const float* __restrict__ ctx,
    const int* __restrict__ lens)
{
    extern __shared__ char smraw[];
    const int tid  = threadIdx.x;
    const int lane = tid & 31;
    const int wid  = tid >> 5;
    const int wm   = wid >> 1;
    const int wn   = wid & 1;
    const int mat  = blockIdx.y;
    const int m0   = blockIdx.x * 128;
    const float* A = (mat == 2) ? x : ctx;
    __half* C = (mat == 0) ? g_Qf : (mat == 1) ? g_Kf : g_Vf;
    const __half* W = g_Wt + (size_t)mat * 131072;

    const uint32_t sbase = smem_u32(smraw);

    float acc[2][8][4];
    #pragma unroll
    for (int mt = 0; mt < 2; mt++)
        #pragma unroll
        for (int nt = 0; nt < 8; nt++)
            #pragma unroll
            for (int j = 0; j < 4; j++) acc[mt][nt][j] = 0.0f;

    const uint32_t a_row  = (uint32_t)(lane & 15);
    const uint32_t a_col2 = (uint32_t)((lane >> 4) << 3) * 2;
    const uint32_t b_row  = (uint32_t)((lane & 7) + ((lane >> 4) << 3));
    const uint32_t b_col2 = (uint32_t)(((lane >> 3) & 1) << 3) * 2;

    float4 ar[4];
    uint4  wr[2];

    auto load_regs = [&](int k0) {
        #pragma unroll
        for (int i = 0; i < 4; i++) {
            int f = tid + i * 256;
            int row = f >> 3, c4 = f & 7;
            ar[i] = *(const float4*)(A + (size_t)(m0 + row) * Ee + k0 + c4 * 4);
        }
        #pragma unroll
        for (int i = 0; i < 2; i++) {
            int f = tid + i * 256;
            int row = f >> 2, q = f & 3;
            wr[i] = *(const uint4*)(W + (size_t)row * Ee + k0 + q * 8);
        }
    };

    auto st_stage = [&](int buf) {
        char* tb = smraw + buf * 20480;
        #pragma unroll
        for (int i = 0; i < 4; i++) {
            int f = tid + i * 256;
            int row = f >> 3, c4 = f & 7;
            float4 v = ar[i];
            uint2 hv;
            hv.x = pack_h2(v.x, v.y);
            hv.y = pack_h2(v.z, v.w);
            *(uint2*)(tb + row * 80 + c4 * 8) = hv;
        }
        #pragma unroll
        for (int i = 0; i < 2; i++) {
            int f = tid + i * 256;
            int row = f >> 2, q = f & 3;
            *(uint4*)(tb + 10240 + row * 80 + q * 16) = wr[i];
        }
    };

    auto do_mma = [&](int buf) {
        const uint32_t st = sbase + buf * 20480;
        #pragma unroll
        for (int ks = 0; ks < 2; ks++) {
            const uint32_t kk2 = ks * 32;
            uint32_t af[2][4];
            #pragma unroll
            for (int mt = 0; mt < 2; mt++) {
                uint32_t r = wm * 32 + mt * 16 + a_row;
                LDMX4(af[mt], st + r * 80 + kk2 + a_col2);
            }
            #pragma unroll
            for (int p = 0; p < 4; p++) {
                uint32_t nr = wn * 64 + p * 16 + b_row;
                uint32_t bh[4];
                LDMX4(bh, st + 10240 + nr * 80 + kk2 + b_col2);
                #pragma unroll
                for (int mt = 0; mt < 2; mt++) {
                    MMAF16(acc[mt][2*p],     af[mt], bh[0], bh[1]);
                    MMAF16(acc[mt][2*p + 1], af[mt], bh[2], bh[3]);
                }
            }
        }
    };

    load_regs(0);
    for (int c = 0; c < 32; c++) {
        st_stage(c & 1);
        __syncthreads();
        if (c < 31) load_regs((c + 1) * 32);
        do_mma(c & 1);
    }

    // Epilogue: /32 (weight prescale), qscale for Q, mask, fp16 store.
    const int lenb = lens[m0 >> 11];
    const float sc = (mat == 0) ? (QSCALE / 32.0f) : (1.0f / 32.0f);
    #pragma unroll
    for (int mt = 0; mt < 2; mt++) {
        int r = m0 + wm * 32 + mt * 16 + (lane >> 2);
        float mk0 = ((((r)     & 2047) < lenb) ? 1.0f : 0.0f) * sc;
        float mk1 = ((((r + 8) & 2047) < lenb) ? 1.0f : 0.0f) * sc;
        #pragma unroll
        for (int nt = 0; nt < 8; nt++) {
            int cc = wn * 64 + nt * 8 + (lane & 3) * 2;
            *(uint32_t*)(C + (size_t)r * Dk + cc) =
                pack_h2(acc[mt][nt][0] * mk0, acc[mt][nt][1] * mk0);
            *(uint32_t*)(C + (size_t)(r + 8) * Dk + cc) =
                pack_h2(acc[mt][nt][2] * mk1, acc[mt][nt][3] * mk1);
        }
    }
}

// ---------------------------------------------------------------------------
// Flash attention: all-fp16 operands, cp.async pipelined.
// BQ=128, BK=64, 8 warps. K double-buffered. smem 105472 B.
// ---------------------------------------------------------------------------
#define AQP 272
#define APP 144
#define SM_Qf 0
#define SM_K  34816     /* + stage*17408 */
#define SM_V  69632
#define SM_P  87040
#define ATTN_SMEM 105472

__global__ __launch_bounds__(256, 1) void attn_mma(
    float* __restrict__ Out, const int* __restrict__ lens)
{
    extern __shared__ char sm[];
    const uint32_t sb = smem_u32(sm);
    const int tid  = threadIdx.x;
    const int lane = tid & 31;
    const int warp = tid >> 5;
    const int b    = blockIdx.y;
    const int q0   = blockIdx.x * 128;
    const int len  = lens[b];

    const uint32_t a_row = lane & 15;
    const uint32_t a_col = (uint32_t)(lane >> 4) * 16;
    const uint32_t b_row = (lane & 7) + ((lane >> 4) << 3);
    const uint32_t b_col = (uint32_t)((lane >> 3) & 1) * 16;
    const uint32_t v_k   = (lane & 7) + ((lane >> 3) & 1) * 8;
    const uint32_t v_d   = (uint32_t)(lane >> 4) * 16;

    auto copy_Q = [&]() {
        #pragma unroll
        for (int i = 0; i < 8; i++) {
            int f = tid + i * 256;          // 0..2047
            int row = f >> 4, c = f & 15;
            cpa16(sb + SM_Qf + row * AQP + c * 16,
                  g_Qf + (size_t)(b * Ll + q0 + row) * Dk + c * 8);
        }
    };
    auto copy_K = [&](int stage, int j0) {
        const uint32_t kb = sb + SM_K + stage * 17408;
        #pragma unroll
        for (int i = 0; i < 4; i++) {
            int f = tid + i * 256;          // 0..1023
            int row = f >> 4, c = f & 15;
            cpa16(kb + row * AQP + c * 16,
                  g_Kf + (size_t)(b * Ll + j0 + row) * Dk + c * 8);
        }
    };
    auto copy_V = [&](int j0) {
        #pragma unroll
        for (int i = 0; i < 4; i++) {
            int f = tid + i * 256;
            int row = f >> 4, c = f & 15;
            cpa16(sb + SM_V + row * AQP + c * 16,
                  g_Vf + (size_t)(b * Ll + j0 + row) * Dk + c * 8);
        }
    };

    float o[16][4];
    #pragma unroll
    for (int nt = 0; nt < 16; nt++)
        #pragma unroll
        for (int j = 0; j < 4; j++) o[nt][j] = 0.0f;
    float mrow[2] = {-1e30f, -1e30f};
    float lrow[2] = {0.0f, 0.0f};

    const int kend = min(len, q0 + 128);

    copy_Q();
    copy_K(0, 0);
    CP_COMMIT;
    CP_WAIT(0);
    __syncthreads();

    int cur = 0;
    for (int j0 = 0; j0 < kend; j0 += 64) {
        // prefetch V(i) — covered by QK MMAs
        copy_V(j0);
        CP_COMMIT;

        // ---- S = Q K^T (16x64 per warp), logits in log2 domain ----
        float s[8][4];
        #pragma unroll
        for (int t = 0; t < 8; t++)
            #pragma unroll
            for (int j = 0; j < 4; j++) s[t][j] = 0.0f;

        const uint32_t kbase = sb + SM_K + cur * 17408;
        #pragma unroll
        for (int ks = 0; ks < 8; ks++) {
            uint32_t qf[4];
            LDMX4(qf, sb + SM_Qf + (warp * 16 + a_row) * AQP + ks * 32 + a_col);
            #pragma unroll
            for (int p = 0; p < 4; p++) {
                uint32_t bh[4];
                LDMX4(bh, kbase + (p * 16 + b_row) * AQP + ks * 32 + b_col);
                MMAF16(s[2*p],     qf, bh[0], bh[1]);
                MMAF16(s[2*p + 1], qf, bh[2], bh[3]);
            }
        }

        // prefetch K(i+1) — covered by softmax + PV
        bool more = (j0 + 64 < kend);
        if (more) {
            copy_K(cur ^ 1, j0 + 64);
            CP_COMMIT;
            CP_WAIT(1);
        } else {
            CP_WAIT(0);
        }
        __syncthreads();

        // ---- mask + online softmax; P -> smem fp16 ----
        #pragma unroll
        for (int h = 0; h < 2; h++) {
            const int qi = q0 + warp * 16 + (lane >> 2) + h * 8;
            float mx = -1e30f;
            #pragma unroll
            for (int t = 0; t < 8; t++) {
                int c = j0 + t * 8 + (lane & 3) * 2;
                float v0 = (c     <= qi && c     < len) ? s[t][2*h]     : -1e30f;
                float v1 = (c + 1 <= qi && c + 1 < len) ? s[t][2*h + 1] : -1e30f;
                s[t][2*h] = v0; s[t][2*h + 1] = v1;
                mx = fmaxf(mx, fmaxf(v0, v1));
            }
            mx = fmaxf(mx, __shfl_xor_sync(0xffffffffu, mx, 1));
            mx = fmaxf(mx, __shfl_xor_sync(0xffffffffu, mx, 2));
            float mnew  = fmaxf(mrow[h], mx);
            float alpha = exp2f(mrow[h] - mnew);
            float lsum  = 0.0f;
            const uint32_t prow = SM_P + (warp * 16 + (lane >> 2) + h * 8) * APP
                                + (lane & 3) * 4;
            #pragma unroll
            for (int t = 0; t < 8; t++) {
                float p0 = exp2f(s[t][2*h]     - mnew);
                float p1 = exp2f(s[t][2*h + 1] - mnew);
                lsum += p0 + p1;
                *(uint32_t*)(sm + prow + t * 16) = pack_h2(p0, p1);
            }
            lsum += __shfl_xor_sync(0xffffffffu, lsum, 1);
            lsum += __shfl_xor_sync(0xffffffffu, lsum, 2);
            lrow[h] = lrow[h] * alpha + lsum;
            mrow[h] = mnew;
            #pragma unroll
            for (int nt = 0; nt < 16; nt++) {
                o[nt][2*h]     *= alpha;
                o[nt][2*h + 1] *= alpha;
            }
        }
        __syncwarp();

        // ---- O += P @ V ----
        #pragma unroll
        for (int ks = 0; ks < 4; ks++) {
            uint32_t pf[4];
            LDMX4(pf, sb + SM_P + (warp * 16 + a_row) * APP + ks * 32 + a_col);
            #pragma unroll
            for (int dt = 0; dt < 8; dt++) {
                uint32_t bh[4];
                LDMX4T(bh, sb + SM_V + (ks * 16 + v_k) * AQP + dt * 32 + v_d);
                MMAF16(o[2*dt],     pf, bh[0], bh[1]);
                MMAF16(o[2*dt + 1], pf, bh[2], bh[3]);
            }
        }
        CP_WAIT(0);
        __syncthreads();
        cur ^= 1;
    }

    // ---- normalize + write ----
    #pragma unroll
    for (int h = 0; h < 2; h++) {
        float inv = 1.0f / lrow[h];
        int row = q0 + warp * 16 + (lane >> 2) + h * 8;
        float* og = Out + ((size_t)(b * Ll + row)) * Dk;
        #pragma unroll
        for (int dt = 0; dt < 16; dt++) {
            float2 v;
            v.x = o[dt][2*h]     * inv;
            v.y = o[dt][2*h + 1] * inv;
            *(float2*)(og + dt * 8 + (lane & 3) * 2) = v;
        }
    }
}

// ---------------------------------------------------------------------------
extern "C" void kernel_launch(void* const* d_in, const int* in_sizes, int n_in,
                              void* d_out, int out_size)
{
    const float* x    = (const float*)d_in[0];
    const float* ctx  = (const float*)d_in[1];
    const int*   lens = (const int*)  d_in[2];
    const float* Wq   = (const float*)d_in[3];
    const float* Wk   = (const float*)d_in[4];
    const float* Wv   = (const float*)d_in[5];
    float* out = (float*)d_out;
    (void)in_sizes; (void)n_in; (void)out_size;

    prep_weights<<<dim3(32, 4, 3), dim3(32, 32)>>>(Wq, Wk, Wv);

    cudaFuncSetAttribute(proj_mma,
                         cudaFuncAttributeMaxDynamicSharedMemorySize, PROJ_SMEM);
    proj_mma<<<dim3(Mtot / 128, 3), 256, PROJ_SMEM>>>(x, ctx, lens);

    cudaFuncSetAttribute(attn_mma,
                         cudaFuncAttributeMaxDynamicSharedMemorySize, ATTN_SMEM);
    attn_mma<<<dim3(Ll / 128, Bb), 256, ATTN_SMEM>>>(out, lens);
}

// round 8
// speedup vs baseline: 9.7337x; 1.1507x over previous
#include <cuda_runtime.h>
#include <cuda_fp16.h>
#include <cstdint>

#define Bb 16
#define Ll 2048
#define Ee 1024
#define Dk 128
#define Mtot (Bb*Ll)   // 32768

// Single fp16 planes: Q (qscale folded), K, V.
__device__ __half g_Qf[Mtot*Dk];
__device__ __half g_Kf[Mtot*Dk];
__device__ __half g_Vf[Mtot*Dk];
// Weights: [mat(3)][N=128][K=1024] fp16, pre-scaled by 32 (epilogue /32).
__device__ __half g_Wt[3 * 128 * 1024];

#define QSCALE 0.12751743f   /* log2(e)/sqrt(128) */

__device__ __forceinline__ uint32_t smem_u32(const void* p) {
    uint32_t a;
    asm("{ .reg .u64 t; cvta.to.shared.u64 t, %1; cvt.u32.u64 %0, t; }"
        : "=r"(a) : "l"(p));
    return a;
}

#define LDMX4(r, addr) \
    asm volatile("ldmatrix.sync.aligned.m8n8.x4.shared.b16 {%0,%1,%2,%3}, [%4];" \
        : "=r"((r)[0]), "=r"((r)[1]), "=r"((r)[2]), "=r"((r)[3]) : "r"(addr))

#define LDMX4T(r, addr) \
    asm volatile("ldmatrix.sync.aligned.m8n8.x4.trans.shared.b16 {%0,%1,%2,%3}, [%4];" \
        : "=r"((r)[0]), "=r"((r)[1]), "=r"((r)[2]), "=r"((r)[3]) : "r"(addr))

#define MMAF16(d, a, b0, b1) \
    asm volatile("mma.sync.aligned.m16n8k16.row.col.f32.f16.f16.f32 " \
        "{%0,%1,%2,%3}, {%4,%5,%6,%7}, {%8,%9}, {%0,%1,%2,%3};" \
        : "+f"((d)[0]), "+f"((d)[1]), "+f"((d)[2]), "+f"((d)[3]) \
        : "r"((a)[0]), "r"((a)[1]), "r"((a)[2]), "r"((a)[3]), "r"(b0), "r"(b1))

#define CP_COMMIT asm volatile("cp.async.commit_group;")
#define CP_WAIT(N) asm volatile("cp.async.wait_group %0;" :: "n"(N))

__device__ __forceinline__ void cpa16(uint32_t dst, const void* src) {
    asm volatile("cp.async.cg.shared.global [%0], [%1], 16;"
                 :: "r"(dst), "l"(src));
}

__device__ __forceinline__ uint32_t pack_h2(float x, float y) {
    __half2 h = __floats2half2_rn(x, y);
    return *(uint32_t*)&h;
}

// ---------------------------------------------------------------------------
// Weight prep: W[1024,128] fp32 -> 32*W fp16, transposed [n][k].
// ---------------------------------------------------------------------------
__global__ void prep_weights(const float* __restrict__ Wq,
                             const float* __restrict__ Wk,
                             const float* __restrict__ Wv)
{
    __shared__ float t[32][33];
    const int mat = blockIdx.z;
    const float* W = (mat == 0) ? Wq : (mat == 1) ? Wk : Wv;
    const int k0 = blockIdx.x * 32, n0 = blockIdx.y * 32;
    const int tx = threadIdx.x, ty = threadIdx.y;
    t[ty][tx] = W[(size_t)(k0 + ty) * Dk + n0 + tx];
    __syncthreads();
    g_Wt[(size_t)mat * 131072 + (size_t)(n0 + ty) * Ee + k0 + tx] =
        __float2half_rn(t[tx][ty] * 32.0f);
}

// ---------------------------------------------------------------------------
// Fused Q+K projection: C[128, 256] = ctx_tile @ [Wq | Wk]; ctx read ONCE.
// 512 threads, 16 warps (4x4), warp tile 32x64. K-chunk 32, double buffered.
// Stage: A 128x32 fp16 (10240 B, pitch 80) | W 256x32 fp16 (20480 B).
// ---------------------------------------------------------------------------
#define PROJQK_SMEM (2 * 30720)

__global__ __launch_bounds__(512, 1) void proj_qk(
    const float* __restrict__ ctx, const int* __restrict__ lens)
{
    extern __shared__ char smraw[];
    const int tid  = threadIdx.x;
    const int lane = tid & 31;
    const int wid  = tid >> 5;
    const int wm   = wid >> 2;      // 0..3 -> 32-row band
    const int wn   = wid & 3;       // 0..3 -> 64-col band of 256
    const int m0   = blockIdx.x * 128;
    const __half* Wq_t = g_Wt;
    const __half* Wk_t = g_Wt + 131072;

    const uint32_t sbase = smem_u32(smraw);

    float acc[2][8][4];
    #pragma unroll
    for (int mt = 0; mt < 2; mt++)
        #pragma unroll
        for (int nt = 0; nt < 8; nt++)
            #pragma unroll
            for (int j = 0; j < 4; j++) acc[mt][nt][j] = 0.0f;

    const uint32_t a_row  = (uint32_t)(lane & 15);
    const uint32_t a_col2 = (uint32_t)((lane >> 4) << 3) * 2;
    const uint32_t b_row  = (uint32_t)((lane & 7) + ((lane >> 4) << 3));
    const uint32_t b_col2 = (uint32_t)(((lane >> 3) & 1) << 3) * 2;

    float4 ar[2];
    uint4  wr[2];

    auto load_regs = [&](int k0) {
        #pragma unroll
        for (int i = 0; i < 2; i++) {
            int f = tid + i * 512;          // 0..1023
            int row = f >> 3, c4 = f & 7;
            ar[i] = *(const float4*)(ctx + (size_t)(m0 + row) * Ee + k0 + c4 * 4);
        }
        #pragma unroll
        for (int i = 0; i < 2; i++) {
            int f = tid + i * 512;          // 0..1023
            int row = f >> 2, q = f & 3;    // row 0..255
            const __half* src = (row < 128)
                ? (Wq_t + (size_t)row * Ee)
                : (Wk_t + (size_t)(row - 128) * Ee);
            wr[i] = *(const uint4*)(src + k0 + q * 8);
        }
    };

    auto st_stage = [&](int buf) {
        char* tb = smraw + buf * 30720;
        #pragma unroll
        for (int i = 0; i < 2; i++) {
            int f = tid + i * 512;
            int row = f >> 3, c4 = f & 7;
            float4 v = ar[i];
            uint2 hv;
            hv.x = pack_h2(v.x, v.y);
            hv.y = pack_h2(v.z, v.w);
            *(uint2*)(tb + row * 80 + c4 * 8) = hv;
        }
        #pragma unroll
        for (int i = 0; i < 2; i++) {
            int f = tid + i * 512;
            int row = f >> 2, q = f & 3;
            *(uint4*)(tb + 10240 + row * 80 + q * 16) = wr[i];
        }
    };

    auto do_mma = [&](int buf) {
        const uint32_t st = sbase + buf * 30720;
        #pragma unroll
        for (int ks = 0; ks < 2; ks++) {
            const uint32_t kk2 = ks * 32;
            uint32_t af[2][4];
            #pragma unroll
            for (int mt = 0; mt < 2; mt++) {
                uint32_t r = wm * 32 + mt * 16 + a_row;
                LDMX4(af[mt], st + r * 80 + kk2 + a_col2);
            }
            #pragma unroll
            for (int p = 0; p < 4; p++) {
                uint32_t nr = wn * 64 + p * 16 + b_row;
                uint32_t bh[4];
                LDMX4(bh, st + 10240 + nr * 80 + kk2 + b_col2);
                #pragma unroll
                for (int mt = 0; mt < 2; mt++) {
                    MMAF16(acc[mt][2*p],     af[mt], bh[0], bh[1]);
                    MMAF16(acc[mt][2*p + 1], af[mt], bh[2], bh[3]);
                }
            }
        }
    };

    load_regs(0);
    for (int c = 0; c < 32; c++) {
        st_stage(c & 1);
        __syncthreads();
        if (c < 31) load_regs((c + 1) * 32);
        do_mma(c & 1);
    }

    // Epilogue: cols [0,128) -> Q (QSCALE/32), cols [128,256) -> K (1/32).
    const int lenb = lens[m0 >> 11];
    const bool isQ = (wn < 2);
    __half* C = isQ ? g_Qf : g_Kf;
    const int ncc = isQ ? wn * 64 : (wn - 2) * 64;
    const float sc = isQ ? (QSCALE / 32.0f) : (1.0f / 32.0f);
    #pragma unroll
    for (int mt = 0; mt < 2; mt++) {
        int r = m0 + wm * 32 + mt * 16 + (lane >> 2);
        float mk0 = ((((r)     & 2047) < lenb) ? 1.0f : 0.0f) * sc;
        float mk1 = ((((r + 8) & 2047) < lenb) ? 1.0f : 0.0f) * sc;
        #pragma unroll
        for (int nt = 0; nt < 8; nt++) {
            int cc = ncc + nt * 8 + (lane & 3) * 2;
            *(uint32_t*)(C + (size_t)r * Dk + cc) =
                pack_h2(acc[mt][nt][0] * mk0, acc[mt][nt][1] * mk0);
            *(uint32_t*)(C + (size_t)(r + 8) * Dk + cc) =
                pack_h2(acc[mt][nt][2] * mk1, acc[mt][nt][3] * mk1);
        }
    }
}

// ---------------------------------------------------------------------------
// V projection: x @ Wv, 256 threads, 8 warps (4x2), as in R7.
// ---------------------------------------------------------------------------
#define PROJV_SMEM (2 * 20480)

__global__ __launch_bounds__(256, 1) void proj_v(
    const float* __restrict__ x, const int* __restrict__ lens)
{
    extern __shared__ char smraw[];
    const int tid  = threadIdx.x;
    const int lane = tid & 31;
    const int wid  = tid >> 5;
    const int wm   = wid >> 1;
    const int wn   = wid & 1;
    const int m0   = blockIdx.x * 128;
    const __half* W = g_Wt + 2 * 131072;

    const uint32_t sbase = smem_u32(smraw);

    float acc[2][8][4];
    #pragma unroll
    for (int mt = 0; mt < 2; mt++)
        #pragma unroll
        for (int nt = 0; nt < 8; nt++)
            #pragma unroll
            for (int j = 0; j < 4; j++) acc[mt][nt][j] = 0.0f;

    const uint32_t a_row  = (uint32_t)(lane & 15);
    const uint32_t a_col2 = (uint32_t)((lane >> 4) << 3) * 2;
    const uint32_t b_row  = (uint32_t)((lane & 7) + ((lane >> 4) << 3));
    const uint32_t b_col2 = (uint32_t)(((lane >> 3) & 1) << 3) * 2;

    float4 ar[4];
    uint4  wr[2];

    auto load_regs = [&](int k0) {
        #pragma unroll
        for (int i = 0; i < 4; i++) {
            int f = tid + i * 256;
            int row = f >> 3, c4 = f & 7;
            ar[i] = *(const float4*)(x + (size_t)(m0 + row) * Ee + k0 + c4 * 4);
        }
        #pragma unroll
        for (int i = 0; i < 2; i++) {
            int f = tid + i * 256;
            int row = f >> 2, q = f & 3;
            wr[i] = *(const uint4*)(W + (size_t)row * Ee + k0 + q * 8);
        }
    };

    auto st_stage = [&](int buf) {
        char* tb = smraw + buf * 20480;
        #pragma unroll
        for (int i = 0; i < 4; i++) {
            int f = tid + i * 256;
            int row = f >> 3, c4 = f & 7;
            float4 v = ar[i];
            uint2 hv;
            hv.x = pack_h2(v.x, v.y);
            hv.y = pack_h2(v.z, v.w);
            *(uint2*)(tb + row * 80 + c4 * 8) = hv;
        }
        #pragma unroll
        for (int i = 0; i < 2; i++) {
            int f = tid + i * 256;
            int row = f >> 2, q = f & 3;
            *(uint4*)(tb + 10240 + row * 80 + q * 16) = wr[i];
        }
    };

    auto do_mma = [&](int buf) {
        const uint32_t st = sbase + buf * 20480;
        #pragma unroll
        for (int ks = 0; ks < 2; ks++) {
            const uint32_t kk2 = ks * 32;
            uint32_t af[2][4];
            #pragma unroll
            for (int mt = 0; mt < 2; mt++) {
                uint32_t r = wm * 32 + mt * 16 + a_row;
                LDMX4(af[mt], st + r * 80 + kk2 + a_col2);
            }
            #pragma unroll
            for (int p = 0; p < 4; p++) {
                uint32_t nr = wn * 64 + p * 16 + b_row;
                uint32_t bh[4];
                LDMX4(bh, st + 10240 + nr * 80 + kk2 + b_col2);
                #pragma unroll
                for (int mt = 0; mt < 2; mt++) {
                    MMAF16(acc[mt][2*p],     af[mt], bh[0], bh[1]);
                    MMAF16(acc[mt][2*p + 1], af[mt], bh[2], bh[3]);
                }
            }
        }
    };

    load_regs(0);
    for (int c = 0; c < 32; c++) {
        st_stage(c & 1);
        __syncthreads();
        if (c < 31) load_regs((c + 1) * 32);
        do_mma(c & 1);
    }

    const int lenb = lens[m0 >> 11];
    const float sc = 1.0f / 32.0f;
    #pragma unroll
    for (int mt = 0; mt < 2; mt++) {
        int r = m0 + wm * 32 + mt * 16 + (lane >> 2);
        float mk0 = ((((r)     & 2047) < lenb) ? 1.0f : 0.0f) * sc;
        float mk1 = ((((r + 8) & 2047) < lenb) ? 1.0f : 0.0f) * sc;
        #pragma unroll
        for (int nt = 0; nt < 8; nt++) {
            int cc = wn * 64 + nt * 8 + (lane & 3) * 2;
            *(uint32_t*)(g_Vf + (size_t)r * Dk + cc) =
                pack_h2(acc[mt][nt][0] * mk0, acc[mt][nt][1] * mk0);
            *(uint32_t*)(g_Vf + (size_t)(r + 8) * Dk + cc) =
                pack_h2(acc[mt][nt][2] * mk1, acc[mt][nt][3] * mk1);
        }
    }
}

// ---------------------------------------------------------------------------
// Flash attention: all-fp16, BQ=128, BK=128, 8 warps, K double-buffered.
// smem: Q 34816 | K 2x34816 | V 34816 | P 34816 = 174080 B.
// ---------------------------------------------------------------------------
#define AQP 272
#define SM_Qf 0
#define SM_K  34816     /* + stage*34816 */
#define SM_V  104448
#define SM_P  139264
#define ATTN_SMEM 174080

__global__ __launch_bounds__(256, 1) void attn_mma(
    float* __restrict__ Out, const int* __restrict__ lens)
{
    extern __shared__ char sm[];
    const uint32_t sb = smem_u32(sm);
    const int tid  = threadIdx.x;
    const int lane = tid & 31;
    const int warp = tid >> 5;
    const int b    = blockIdx.y;
    const int q0   = blockIdx.x * 128;
    const int len  = lens[b];

    const uint32_t a_row = lane & 15;
    const uint32_t a_col = (uint32_t)(lane >> 4) * 16;
    const uint32_t b_row = (lane & 7) + ((lane >> 4) << 3);
    const uint32_t b_col = (uint32_t)((lane >> 3) & 1) * 16;
    const uint32_t v_k   = (lane & 7) + ((lane >> 3) & 1) * 8;
    const uint32_t v_d   = (uint32_t)(lane >> 4) * 16;

    auto copy_Q = [&]() {
        #pragma unroll
        for (int i = 0; i < 8; i++) {
            int f = tid + i * 256;          // 0..2047
            int row = f >> 4, c = f & 15;
            cpa16(sb + SM_Qf + row * AQP + c * 16,
                  g_Qf + (size_t)(b * Ll + q0 + row) * Dk + c * 8);
        }
    };
    auto copy_K = [&](int stage, int j0) {
        const uint32_t kb = sb + SM_K + stage * 34816;
        #pragma unroll
        for (int i = 0; i < 8; i++) {
            int f = tid + i * 256;          // 0..2047 (128 rows)
            int row = f >> 4, c = f & 15;
            cpa16(kb + row * AQP + c * 16,
                  g_Kf + (size_t)(b * Ll + j0 + row) * Dk + c * 8);
        }
    };
    auto copy_V = [&](int j0) {
        #pragma unroll
        for (int i = 0; i < 8; i++) {
            int f = tid + i * 256;
            int row = f >> 4, c = f & 15;
            cpa16(sb + SM_V + row * AQP + c * 16,
                  g_Vf + (size_t)(b * Ll + j0 + row) * Dk + c * 8);
        }
    };

    float o[16][4];
    #pragma unroll
    for (int nt = 0; nt < 16; nt++)
        #pragma unroll
        for (int j = 0; j < 4; j++) o[nt][j] = 0.0f;
    float mrow[2] = {-1e30f, -1e30f};
    float lrow[2] = {0.0f, 0.0f};

    const int kend = min(len, q0 + 128);

    copy_Q();
    copy_K(0, 0);
    CP_COMMIT;
    CP_WAIT(0);
    __syncthreads();

    int cur = 0;
    for (int j0 = 0; j0 < kend; j0 += 128) {
        // prefetch V(i) — covered by QK MMAs
        copy_V(j0);
        CP_COMMIT;

        // ---- S = Q K^T (16x128 per warp), logits in log2 domain ----
        float s[16][4];
        #pragma unroll
        for (int t = 0; t < 16; t++)
            #pragma unroll
            for (int j = 0; j < 4; j++) s[t][j] = 0.0f;

        const uint32_t kbase = sb + SM_K + cur * 34816;
        #pragma unroll
        for (int ks = 0; ks < 8; ks++) {
            uint32_t qf[4];
            LDMX4(qf, sb + SM_Qf + (warp * 16 + a_row) * AQP + ks * 32 + a_col);
            #pragma unroll
            for (int p = 0; p < 8; p++) {
                uint32_t bh[4];
                LDMX4(bh, kbase + (p * 16 + b_row) * AQP + ks * 32 + b_col);
                MMAF16(s[2*p],     qf, bh[0], bh[1]);
                MMAF16(s[2*p + 1], qf, bh[2], bh[3]);
            }
        }

        // prefetch K(i+1) — covered by softmax + PV
        bool more = (j0 + 128 < kend);
        if (more) {
            copy_K(cur ^ 1, j0 + 128);
            CP_COMMIT;
            CP_WAIT(1);
        } else {
            CP_WAIT(0);
        }
        __syncthreads();

        // ---- mask + online softmax; P -> smem fp16 ----
        #pragma unroll
        for (int h = 0; h < 2; h++) {
            const int qi = q0 + warp * 16 + (lane >> 2) + h * 8;
            float mx = -1e30f;
            #pragma unroll
            for (int t = 0; t < 16; t++) {
                int c = j0 + t * 8 + (lane & 3) * 2;
                float v0 = (c     <= qi && c     < len) ? s[t][2*h]     : -1e30f;
                float v1 = (c + 1 <= qi && c + 1 < len) ? s[t][2*h + 1] : -1e30f;
                s[t][2*h] = v0; s[t][2*h + 1] = v1;
                mx = fmaxf(mx, fmaxf(v0, v1));
            }
            mx = fmaxf(mx, __shfl_xor_sync(0xffffffffu, mx, 1));
            mx = fmaxf(mx, __shfl_xor_sync(0xffffffffu, mx, 2));
            float mnew  = fmaxf(mrow[h], mx);
            float alpha = exp2f(mrow[h] - mnew);
            float lsum  = 0.0f;
            const uint32_t prow = SM_P + (warp * 16 + (lane >> 2) + h * 8) * AQP
                                + (lane & 3) * 4;
            #pragma unroll
            for (int t = 0; t < 16; t++) {
                float p0 = exp2f(s[t][2*h]     - mnew);
                float p1 = exp2f(s[t][2*h + 1] - mnew);
                lsum += p0 + p1;
                *(uint32_t*)(sm + prow + t * 16) = pack_h2(p0, p1);
            }
            lsum += __shfl_xor_sync(0xffffffffu, lsum, 1);
            lsum += __shfl_xor_sync(0xffffffffu, lsum, 2);
            lrow[h] = lrow[h] * alpha + lsum;
            mrow[h] = mnew;
            #pragma unroll
            for (int nt = 0; nt < 16; nt++) {
                o[nt][2*h]     *= alpha;
                o[nt][2*h + 1] *= alpha;
            }
        }
        __syncwarp();

        // ---- O += P @ V ----
        #pragma unroll
        for (int ks = 0; ks < 8; ks++) {
            uint32_t pf[4];
            LDMX4(pf, sb + SM_P + (warp * 16 + a_row) * AQP + ks * 32 + a_col);
            #pragma unroll
            for (int dt = 0; dt < 8; dt++) {
                uint32_t bh[4];
                LDMX4T(bh, sb + SM_V + (ks * 16 + v_k) * AQP + dt * 32 + v_d);
                MMAF16(o[2*dt],     pf, bh[0], bh[1]);
                MMAF16(o[2*dt + 1], pf, bh[2], bh[3]);
            }
        }
        CP_WAIT(0);
        __syncthreads();
        cur ^= 1;
    }

    // ---- normalize + write ----
    #pragma unroll
    for (int h = 0; h < 2; h++) {
        float inv = 1.0f / lrow[h];
        int row = q0 + warp * 16 + (lane >> 2) + h * 8;
        float* og = Out + ((size_t)(b * Ll + row)) * Dk;
        #pragma unroll
        for (int dt = 0; dt < 16; dt++) {
            float2 v;
            v.x = o[dt][2*h]     * inv;
            v.y = o[dt][2*h + 1] * inv;
            *(float2*)(og + dt * 8 + (lane & 3) * 2) = v;
        }
    }
}

// ---------------------------------------------------------------------------
extern "C" void kernel_launch(void* const* d_in, const int* in_sizes, int n_in,
                              void* d_out, int out_size)
{
    const float* x    = (const float*)d_in[0];
    const float* ctx  = (const float*)d_in[1];
    const int*   lens = (const int*)  d_in[2];
    const float* Wq   = (const float*)d_in[3];
    const float* Wk   = (const float*)d_in[4];
    const float* Wv   = (const float*)d_in[5];
    float* out = (float*)d_out;
    (void)in_sizes; (void)n_in; (void)out_size;

    prep_weights<<<dim3(32, 4, 3), dim3(32, 32)>>>(Wq, Wk, Wv);

    cudaFuncSetAttribute(proj_qk,
                         cudaFuncAttributeMaxDynamicSharedMemorySize, PROJQK_SMEM);
    proj_qk<<<Mtot / 128, 512, PROJQK_SMEM>>>(ctx, lens);

    cudaFuncSetAttribute(proj_v,
                         cudaFuncAttributeMaxDynamicSharedMemorySize, PROJV_SMEM);
    proj_v<<<Mtot / 128, 256, PROJV_SMEM>>>(x, lens);

    cudaFuncSetAttribute(attn_mma,
                         cudaFuncAttributeMaxDynamicSharedMemorySize, ATTN_SMEM);
    attn_mma<<<dim3(Ll / 128, Bb), 256, ATTN_SMEM>>>(out, lens);
}